// round 1
// baseline (speedup 1.0000x reference)
#include <cuda_runtime.h>
#include <cuda_bf16.h>
#include <math.h>

// ---------------------------------------------------------------------------
// Problem constants
// ---------------------------------------------------------------------------
#define S_TOK   2048      // total tokens (noisy + clean)
#define N_TOK   1024      // tokens per half
#define D_MODEL 1024
#define H_HEADS 16
#define HD      64        // head dim
#define D_MLP   4096
#define COND    128
#define BSZ     16        // diffusion block size

// ---------------------------------------------------------------------------
// Device scratch (static __device__ arrays — no allocation)
// ---------------------------------------------------------------------------
__device__ float g_mods[6 * D_MODEL];                  // adaLN outputs
__device__ float g_h   [S_TOK * D_MODEL];              // LN1+mod output
__device__ float g_qkv [S_TOK * 3 * D_MODEL];          // raw qkv
__device__ float g_Q   [H_HEADS * S_TOK * HD];         // rotary'd, head-major
__device__ float g_K   [H_HEADS * S_TOK * HD];
__device__ float g_V   [H_HEADS * S_TOK * HD];
__device__ float g_O   [S_TOK * D_MODEL];              // attention out, [S, D]
__device__ float g_x2  [S_TOK * D_MODEL];              // post-attn residual
__device__ float g_h2  [S_TOK * D_MODEL];              // LN2+mod output
__device__ float g_m1  [S_TOK * D_MLP];                // MLP hidden

// ---------------------------------------------------------------------------
// adaLN: mods[i] = dot(adaLN_w[i, :128], c) + adaLN_b[i],  i in [0, 6144)
// ---------------------------------------------------------------------------
__global__ void adaln_kernel(const float* __restrict__ c,
                             const float* __restrict__ W,
                             const float* __restrict__ b) {
    __shared__ float cs[COND];
    int tid = threadIdx.x;
    if (tid < COND) cs[tid] = c[tid];
    __syncthreads();
    int i = blockIdx.x * blockDim.x + tid;
    if (i >= 6 * D_MODEL) return;
    const float* w = W + (size_t)i * COND;
    float acc = 0.f;
#pragma unroll 8
    for (int j = 0; j < COND; j++) acc += w[j] * cs[j];
    g_mods[i] = acc + b[i];
}

// ---------------------------------------------------------------------------
// LayerNorm (no bias) + adaLN modulate: out = LN(x)*w*(1+sc) + sh
// one block (256 threads) per row of 1024
// ---------------------------------------------------------------------------
__inline__ __device__ float warp_reduce_sum(float v) {
#pragma unroll
    for (int o = 16; o > 0; o >>= 1) v += __shfl_xor_sync(0xffffffffu, v, o);
    return v;
}

__global__ void ln_mod_kernel(const float* __restrict__ X,
                              const float* __restrict__ w,
                              const float* __restrict__ sc,
                              const float* __restrict__ sh,
                              float* __restrict__ out) {
    int row = blockIdx.x;
    const float4* x4 = (const float4*)(X + (size_t)row * D_MODEL);
    int tid = threadIdx.x;
    float4 v = x4[tid];
    float s  = v.x + v.y + v.z + v.w;
    float ss = v.x*v.x + v.y*v.y + v.z*v.z + v.w*v.w;
    __shared__ float red_s[8], red_ss[8];
    s  = warp_reduce_sum(s);
    ss = warp_reduce_sum(ss);
    int wid = tid >> 5, lid = tid & 31;
    if (lid == 0) { red_s[wid] = s; red_ss[wid] = ss; }
    __syncthreads();
    if (wid == 0) {
        float a = (lid < 8) ? red_s[lid]  : 0.f;
        float b = (lid < 8) ? red_ss[lid] : 0.f;
        a = warp_reduce_sum(a);
        b = warp_reduce_sum(b);
        if (lid == 0) { red_s[0] = a; red_ss[0] = b; }
    }
    __syncthreads();
    float mu  = red_s[0] * (1.f / D_MODEL);
    float var = red_ss[0] * (1.f / D_MODEL) - mu * mu;
    float inv = rsqrtf(var + 1e-5f);
    int d0 = tid * 4;
    float* o = out + (size_t)row * D_MODEL;
    float vv[4] = {v.x, v.y, v.z, v.w};
#pragma unroll
    for (int i = 0; i < 4; i++) {
        int d = d0 + i;
        o[d] = (vv[i] - mu) * inv * w[d] * (1.f + sc[d]) + sh[d];
    }
}

// ---------------------------------------------------------------------------
// Tiled fp32 GEMM: C[M,N] = A[M,K] @ W[N,K]^T (+ epilogue)
// BM=BN=128, BK=16, 256 threads, 8x8 register microtile
// EPI: 0 none, 1 gate*acc+res, 2 gelu(acc+bias), 3 gate*(acc+bias)+res
// ---------------------------------------------------------------------------
__device__ __forceinline__ float gelu_tanh(float x) {
    float x3 = x * x * x;
    return 0.5f * x * (1.f + tanhf(0.7978845608028654f * (x + 0.044715f * x3)));
}

template<int EPI>
__global__ void __launch_bounds__(256, 2)
gemm_kernel(const float* __restrict__ A, const float* __restrict__ W,
            float* __restrict__ C, int M, int N, int K,
            const float* __restrict__ bias,
            const float* __restrict__ gate,
            const float* __restrict__ res) {
    __shared__ float As[16][132];
    __shared__ float Ws[16][132];
    const int m0 = blockIdx.y * 128;
    const int n0 = blockIdx.x * 128;
    const int tid = threadIdx.x;
    const int tm = tid >> 4;       // 0..15
    const int tn = tid & 15;       // 0..15
    float acc[8][8] = {};

    for (int k0 = 0; k0 < K; k0 += 16) {
#pragma unroll
        for (int i = 0; i < 2; i++) {
            int f   = tid + i * 256;     // float4 slot, 0..511
            int row = f >> 2;            // 0..127
            int kc  = (f & 3) * 4;       // 0,4,8,12
            float4 va = *(const float4*)&A[(size_t)(m0 + row) * K + k0 + kc];
            As[kc+0][row] = va.x; As[kc+1][row] = va.y;
            As[kc+2][row] = va.z; As[kc+3][row] = va.w;
            float4 vw = *(const float4*)&W[(size_t)(n0 + row) * K + k0 + kc];
            Ws[kc+0][row] = vw.x; Ws[kc+1][row] = vw.y;
            Ws[kc+2][row] = vw.z; Ws[kc+3][row] = vw.w;
        }
        __syncthreads();
#pragma unroll
        for (int k = 0; k < 16; k++) {
            float a[8], b[8];
            float4 a0 = *(const float4*)&As[k][tm * 8];
            float4 a1 = *(const float4*)&As[k][tm * 8 + 4];
            a[0]=a0.x; a[1]=a0.y; a[2]=a0.z; a[3]=a0.w;
            a[4]=a1.x; a[5]=a1.y; a[6]=a1.z; a[7]=a1.w;
            float4 b0 = *(const float4*)&Ws[k][tn * 8];
            float4 b1 = *(const float4*)&Ws[k][tn * 8 + 4];
            b[0]=b0.x; b[1]=b0.y; b[2]=b0.z; b[3]=b0.w;
            b[4]=b1.x; b[5]=b1.y; b[6]=b1.z; b[7]=b1.w;
#pragma unroll
            for (int i = 0; i < 8; i++)
#pragma unroll
                for (int j = 0; j < 8; j++)
                    acc[i][j] += a[i] * b[j];
        }
        __syncthreads();
    }

#pragma unroll
    for (int i = 0; i < 8; i++) {
        int row = m0 + tm * 8 + i;
#pragma unroll
        for (int j = 0; j < 8; j++) {
            int col = n0 + tn * 8 + j;
            float v = acc[i][j];
            if (EPI == 1) v = gate[col] * v + res[(size_t)row * N + col];
            else if (EPI == 2) v = gelu_tanh(v + bias[col]);
            else if (EPI == 3) v = gate[col] * (v + bias[col]) + res[(size_t)row * N + col];
            C[(size_t)row * N + col] = v;
        }
    }
}

// ---------------------------------------------------------------------------
// Rotary (applied to q, k AND v, positions = token index mod N) + transpose to
// head-major [H][S][HD]
// ---------------------------------------------------------------------------
__global__ void rope_kernel(const float* __restrict__ cosT,
                            const float* __restrict__ sinT) {
    int idx = blockIdx.x * blockDim.x + threadIdx.x;   // over S * H * 32
    if (idx >= S_TOK * H_HEADS * 32) return;
    int hd2 = idx & 31;
    int h   = (idx >> 5) & (H_HEADS - 1);
    int s   = idx >> 9;
    int p   = s & (N_TOK - 1);
    float cs = cosT[p * 32 + hd2];
    float sn = sinT[p * 32 + hd2];
    const float* src = g_qkv + (size_t)s * 3 * D_MODEL + h * HD;
#pragma unroll
    for (int qi = 0; qi < 3; qi++) {
        float x1 = src[qi * D_MODEL + hd2];
        float x2 = src[qi * D_MODEL + hd2 + 32];
        float o1 = x1 * cs - x2 * sn;
        float o2 = x2 * cs + x1 * sn;
        float* dst = (qi == 0 ? g_Q : qi == 1 ? g_K : g_V)
                   + ((size_t)h * S_TOK + s) * HD;
        dst[hd2]      = o1;
        dst[hd2 + 32] = o2;
    }
}

// ---------------------------------------------------------------------------
// Block-diffusion attention, flash-style online softmax.
// CTA = one (16-query block, head). The mask reduces to CONTIGUOUS key ranges:
//   qb < 64 (noisy):  keys [qb*16, qb*16+16)  U  [1024, 1024 + qb*16)
//   qb >= 64 (clean): keys [1024, 1024 + (qb-63)*16)
// 128 threads: thread t -> (qi = t/8, r8 = t%8); owns O[qi][r8*8 .. r8*8+8)
// ---------------------------------------------------------------------------
__global__ void __launch_bounds__(128)
attn_kernel(float* __restrict__ O) {
    int qb = blockIdx.x;           // 0..127
    int h  = blockIdx.y;           // 0..15
    int t  = threadIdx.x;
    int qi = t >> 3;
    int r8 = t & 7;

    __shared__ float Qs[16][64];
    __shared__ float Ks[16][64];
    __shared__ float Vs[16][64];
    __shared__ float Ssc[16][16];
    __shared__ float Mrow[16], Lrow[16], Sfac[16];

    const float* Qh = g_Q + (size_t)h * S_TOK * HD;
    const float* Kh = g_K + (size_t)h * S_TOK * HD;
    const float* Vh = g_V + (size_t)h * S_TOK * HD;
    int q0 = qb * 16;

    for (int i = t; i < 16 * 64; i += 128)
        Qs[i >> 6][i & 63] = Qh[(size_t)(q0 + (i >> 6)) * HD + (i & 63)] * 0.125f;
    if (t < 16) { Mrow[t] = -INFINITY; Lrow[t] = 0.f; }
    __syncthreads();

    float qreg[64];
#pragma unroll
    for (int d = 0; d < 64; d++) qreg[d] = Qs[qi][d];

    float Oacc[8] = {0.f, 0.f, 0.f, 0.f, 0.f, 0.f, 0.f, 0.f};

    int rA0, rA1, rB0, rB1;
    if (qb < 64) { rA0 = q0;    rA1 = q0 + 16;            rB0 = N_TOK; rB1 = N_TOK + qb * 16; }
    else         { rA0 = N_TOK; rA1 = N_TOK + (qb-63)*16; rB0 = 0;     rB1 = 0; }

#pragma unroll 1
    for (int rng = 0; rng < 2; rng++) {
        int r0 = (rng == 0) ? rA0 : rB0;
        int r1 = (rng == 0) ? rA1 : rB1;
#pragma unroll 1
        for (int k0 = r0; k0 < r1; k0 += 16) {
            __syncthreads();   // protect Ks/Vs/Ssc from previous iteration
            for (int i = t; i < 16 * 64; i += 128) {
                int kr = i >> 6, d = i & 63;
                Ks[kr][d] = Kh[(size_t)(k0 + kr) * HD + d];
                Vs[kr][d] = Vh[(size_t)(k0 + kr) * HD + d];
            }
            __syncthreads();

            // scores: this thread does keys r8 and r8+8 for row qi
            float s0 = 0.f, s1 = 0.f;
#pragma unroll
            for (int d = 0; d < 64; d++) {
                float q = qreg[d];
                s0 += q * Ks[r8][d];
                s1 += q * Ks[r8 + 8][d];
            }
            Ssc[qi][r8]     = s0;
            Ssc[qi][r8 + 8] = s1;
            __syncthreads();

            if (t < 16) {
                float m = Mrow[t];
                float cmax = m;
#pragma unroll
                for (int j = 0; j < 16; j++) cmax = fmaxf(cmax, Ssc[t][j]);
                float corr = __expf(m - cmax);
                float l = Lrow[t] * corr;
#pragma unroll
                for (int j = 0; j < 16; j++) {
                    float p = __expf(Ssc[t][j] - cmax);
                    Ssc[t][j] = p;
                    l += p;
                }
                Mrow[t] = cmax; Lrow[t] = l; Sfac[t] = corr;
            }
            __syncthreads();

            float corr = Sfac[qi];
#pragma unroll
            for (int i = 0; i < 8; i++) Oacc[i] *= corr;
#pragma unroll
            for (int j = 0; j < 16; j++) {
                float p = Ssc[qi][j];
#pragma unroll
                for (int i = 0; i < 8; i++)
                    Oacc[i] += p * Vs[j][r8 * 8 + i];
            }
        }
    }

    float invl = 1.f / Lrow[qi];
    int row = q0 + qi;
#pragma unroll
    for (int i = 0; i < 8; i++)
        O[(size_t)row * D_MODEL + h * HD + r8 * 8 + i] = Oacc[i] * invl;
}

// ---------------------------------------------------------------------------
// kernel_launch
// inputs: 0 x, 1 c, 2 cos, 3 sin, 4 norm1_w, 5 qkv_w, 6 attn_out_w, 7 norm2_w,
//         8 mlp_w1, 9 mlp_b1, 10 mlp_w2, 11 mlp_b2, 12 adaLN_w, 13 adaLN_b
// ---------------------------------------------------------------------------
extern "C" void kernel_launch(void* const* d_in, const int* in_sizes, int n_in,
                              void* d_out, int out_size) {
    const float* x          = (const float*)d_in[0];
    const float* c          = (const float*)d_in[1];
    const float* cosT       = (const float*)d_in[2];
    const float* sinT       = (const float*)d_in[3];
    const float* norm1_w    = (const float*)d_in[4];
    const float* qkv_w      = (const float*)d_in[5];
    const float* attn_out_w = (const float*)d_in[6];
    const float* norm2_w    = (const float*)d_in[7];
    const float* mlp_w1     = (const float*)d_in[8];
    const float* mlp_b1     = (const float*)d_in[9];
    const float* mlp_w2     = (const float*)d_in[10];
    const float* mlp_b2     = (const float*)d_in[11];
    const float* adaLN_w    = (const float*)d_in[12];
    const float* adaLN_b    = (const float*)d_in[13];
    float* out = (float*)d_out;

    float *mods, *h, *Obuf, *x2, *h2, *m1, *qkv;
    cudaGetSymbolAddress((void**)&mods, g_mods);
    cudaGetSymbolAddress((void**)&h,    g_h);
    cudaGetSymbolAddress((void**)&qkv,  g_qkv);
    cudaGetSymbolAddress((void**)&Obuf, g_O);
    cudaGetSymbolAddress((void**)&x2,   g_x2);
    cudaGetSymbolAddress((void**)&h2,   g_h2);
    cudaGetSymbolAddress((void**)&m1,   g_m1);

    const float* sh_msa = mods + 0 * D_MODEL;
    const float* sc_msa = mods + 1 * D_MODEL;
    const float* g_msa  = mods + 2 * D_MODEL;
    const float* sh_mlp = mods + 3 * D_MODEL;
    const float* sc_mlp = mods + 4 * D_MODEL;
    const float* g_mlp  = mods + 5 * D_MODEL;

    // 1. adaLN modulation vector
    adaln_kernel<<<(6 * D_MODEL + 127) / 128, 128>>>(c, adaLN_w, adaLN_b);

    // 2. LN1 + modulate
    ln_mod_kernel<<<S_TOK, 256>>>(x, norm1_w, sc_msa, sh_msa, h);

    // 3. QKV GEMM: [2048,1024] @ [3072,1024]^T
    gemm_kernel<0><<<dim3(3 * D_MODEL / 128, S_TOK / 128), 256>>>(
        h, qkv_w, qkv, S_TOK, 3 * D_MODEL, D_MODEL, nullptr, nullptr, nullptr);

    // 4. RoPE (q, k, v) + head-major transpose
    rope_kernel<<<(S_TOK * H_HEADS * 32 + 255) / 256, 256>>>(cosT, sinT);

    // 5. Block-diffusion attention
    attn_kernel<<<dim3(S_TOK / 16, H_HEADS), 128>>>(Obuf);

    // 6. Output projection + gated residual: x2 = g_msa * (O @ Wo^T) + x
    gemm_kernel<1><<<dim3(D_MODEL / 128, S_TOK / 128), 256>>>(
        Obuf, attn_out_w, x2, S_TOK, D_MODEL, D_MODEL, nullptr, g_msa, x);

    // 7. LN2 + modulate
    ln_mod_kernel<<<S_TOK, 256>>>(x2, norm2_w, sc_mlp, sh_mlp, h2);

    // 8. MLP up + GELU
    gemm_kernel<2><<<dim3(D_MLP / 128, S_TOK / 128), 256>>>(
        h2, mlp_w1, m1, S_TOK, D_MLP, D_MODEL, mlp_b1, nullptr, nullptr);

    // 9. MLP down + gated residual: out = g_mlp * (m1 @ W2^T + b2) + x2
    gemm_kernel<3><<<dim3(D_MODEL / 128, S_TOK / 128), 256>>>(
        m1, mlp_w2, out, S_TOK, D_MODEL, D_MLP, mlp_b2, g_mlp, x2);
}

// round 3
// speedup vs baseline: 2.6757x; 2.6757x over previous
#include <cuda_runtime.h>
#include <cuda_bf16.h>
#include <math.h>

// ---------------------------------------------------------------------------
// Problem constants
// ---------------------------------------------------------------------------
#define S_TOK   2048
#define N_TOK   1024
#define D_MODEL 1024
#define H_HEADS 16
#define HD      64
#define D_MLP   4096
#define COND    128
#define BSZ     16

// ---------------------------------------------------------------------------
// Device scratch
// ---------------------------------------------------------------------------
__device__ float g_mods[6 * D_MODEL];
__device__ float g_h   [S_TOK * D_MODEL];
__device__ float g_qkv [S_TOK * 3 * D_MODEL];
__device__ float g_Q   [H_HEADS * S_TOK * HD];
__device__ float g_K   [H_HEADS * S_TOK * HD];
__device__ float g_V   [H_HEADS * S_TOK * HD];
__device__ float g_O   [S_TOK * D_MODEL];
__device__ float g_x2  [S_TOK * D_MODEL];
__device__ float g_h2  [S_TOK * D_MODEL];
__device__ float g_m1  [S_TOK * D_MLP];

// ---------------------------------------------------------------------------
// adaLN
// ---------------------------------------------------------------------------
__global__ void adaln_kernel(const float* __restrict__ c,
                             const float* __restrict__ W,
                             const float* __restrict__ b) {
    __shared__ float cs[COND];
    int tid = threadIdx.x;
    if (tid < COND) cs[tid] = c[tid];
    __syncthreads();
    int i = blockIdx.x * blockDim.x + tid;
    if (i >= 6 * D_MODEL) return;
    const float* w = W + (size_t)i * COND;
    float acc = 0.f;
#pragma unroll 8
    for (int j = 0; j < COND; j++) acc += w[j] * cs[j];
    g_mods[i] = acc + b[i];
}

// ---------------------------------------------------------------------------
// LayerNorm + modulate
// ---------------------------------------------------------------------------
__inline__ __device__ float warp_reduce_sum(float v) {
#pragma unroll
    for (int o = 16; o > 0; o >>= 1) v += __shfl_xor_sync(0xffffffffu, v, o);
    return v;
}

__global__ void ln_mod_kernel(const float* __restrict__ X,
                              const float* __restrict__ w,
                              const float* __restrict__ sc,
                              const float* __restrict__ sh,
                              float* __restrict__ out) {
    int row = blockIdx.x;
    const float4* x4 = (const float4*)(X + (size_t)row * D_MODEL);
    int tid = threadIdx.x;
    float4 v = x4[tid];
    float s  = v.x + v.y + v.z + v.w;
    float ss = v.x*v.x + v.y*v.y + v.z*v.z + v.w*v.w;
    __shared__ float red_s[8], red_ss[8];
    s  = warp_reduce_sum(s);
    ss = warp_reduce_sum(ss);
    int wid = tid >> 5, lid = tid & 31;
    if (lid == 0) { red_s[wid] = s; red_ss[wid] = ss; }
    __syncthreads();
    if (wid == 0) {
        float a = (lid < 8) ? red_s[lid]  : 0.f;
        float b = (lid < 8) ? red_ss[lid] : 0.f;
        a = warp_reduce_sum(a);
        b = warp_reduce_sum(b);
        if (lid == 0) { red_s[0] = a; red_ss[0] = b; }
    }
    __syncthreads();
    float mu  = red_s[0] * (1.f / D_MODEL);
    float var = red_ss[0] * (1.f / D_MODEL) - mu * mu;
    float inv = rsqrtf(var + 1e-5f);
    int d0 = tid * 4;
    float* o = out + (size_t)row * D_MODEL;
    float vv[4] = {v.x, v.y, v.z, v.w};
#pragma unroll
    for (int i = 0; i < 4; i++) {
        int d = d0 + i;
        o[d] = (vv[i] - mu) * inv * w[d] * (1.f + sc[d]) + sh[d];
    }
}

// ---------------------------------------------------------------------------
// TF32 tensor-core GEMM: C[M,N] = A[M,K] @ W[N,K]^T (+ epilogue)
// CTA 128x128, 4 warps (2x2) each 64x64, BK=16, double-buffered smem.
// Swizzle addr(k,m) = k*136 + ((m + 8*(k>>2)) & 127): conflict-free for both
// the staging stores and the mma fragment loads.
// EPI: 0 none, 1 gate*acc+res, 2 gelu(acc+bias), 3 gate*(acc+bias)+res
// ---------------------------------------------------------------------------
__device__ __forceinline__ float gelu_tanh(float x) {
    float x3 = x * x * x;
    return 0.5f * x * (1.f + tanhf(0.7978845608028654f * (x + 0.044715f * x3)));
}

__device__ __forceinline__ unsigned f2tf(float f) {
    unsigned r;
    asm("cvt.rna.tf32.f32 %0, %1;" : "=r"(r) : "f"(f));
    return r;
}

__device__ __forceinline__ int swz(int k, int m) {
    return k * 136 + ((m + ((k >> 2) << 3)) & 127);
}

__device__ __forceinline__ void mma_tf32(float* c, const unsigned* a, const unsigned* b) {
    asm volatile(
        "mma.sync.aligned.m16n8k8.row.col.f32.tf32.tf32.f32 "
        "{%0,%1,%2,%3}, {%4,%5,%6,%7}, {%8,%9}, {%0,%1,%2,%3};\n"
        : "+f"(c[0]), "+f"(c[1]), "+f"(c[2]), "+f"(c[3])
        : "r"(a[0]), "r"(a[1]), "r"(a[2]), "r"(a[3]), "r"(b[0]), "r"(b[1]));
}

template<int EPI>
__global__ void __launch_bounds__(128, 2)
gemm_tc(const float* __restrict__ A, const float* __restrict__ W,
        float* __restrict__ C, int M, int N, int K,
        const float* __restrict__ bias,
        const float* __restrict__ gate,
        const float* __restrict__ res) {
    __shared__ unsigned As[2][16 * 136];
    __shared__ unsigned Bs[2][16 * 136];

    const int m0 = blockIdx.y * 128;
    const int n0 = blockIdx.x * 128;
    const int tid = threadIdx.x;
    const int lane = tid & 31;
    const int warp = tid >> 5;
    const int wm = (warp >> 1) * 64;
    const int wn = (warp & 1) * 64;
    const int g  = lane >> 2;
    const int tg = lane & 3;

    const int sr = tid >> 2;
    const int sc = (tid & 3) * 4;

    float acc[4][8][4] = {};
    float4 ra[4], rb[4];

    const int nTiles = K / 16;

    // prologue load tile 0
#pragma unroll
    for (int i = 0; i < 4; i++) {
        int r = sr + i * 32;
        ra[i] = *(const float4*)&A[(size_t)(m0 + r) * K + sc];
        rb[i] = *(const float4*)&W[(size_t)(n0 + r) * K + sc];
    }
    {
        unsigned* sA = As[0];
        unsigned* sB = Bs[0];
#pragma unroll
        for (int i = 0; i < 4; i++) {
            int r = sr + i * 32;
            int mo = (r + 8 * (sc >> 2)) & 127;
            float va[4] = {ra[i].x, ra[i].y, ra[i].z, ra[i].w};
            float vb[4] = {rb[i].x, rb[i].y, rb[i].z, rb[i].w};
#pragma unroll
            for (int u = 0; u < 4; u++) {
                sA[(sc + u) * 136 + mo] = f2tf(va[u]);
                sB[(sc + u) * 136 + mo] = f2tf(vb[u]);
            }
        }
    }
    __syncthreads();

    for (int t = 0; t < nTiles; t++) {
        int cur = t & 1;
        if (t + 1 < nTiles) {
            int k0 = (t + 1) * 16;
#pragma unroll
            for (int i = 0; i < 4; i++) {
                int r = sr + i * 32;
                ra[i] = *(const float4*)&A[(size_t)(m0 + r) * K + k0 + sc];
                rb[i] = *(const float4*)&W[(size_t)(n0 + r) * K + k0 + sc];
            }
        }

        const unsigned* sA = As[cur];
        const unsigned* sB = Bs[cur];
#pragma unroll
        for (int kk = 0; kk < 16; kk += 8) {
            unsigned af[4][4], bf[8][2];
#pragma unroll
            for (int i = 0; i < 4; i++) {
                int m = wm + i * 16 + g;
                af[i][0] = sA[swz(kk + tg,     m)];
                af[i][1] = sA[swz(kk + tg,     m + 8)];
                af[i][2] = sA[swz(kk + tg + 4, m)];
                af[i][3] = sA[swz(kk + tg + 4, m + 8)];
            }
#pragma unroll
            for (int j = 0; j < 8; j++) {
                int n = wn + j * 8 + g;
                bf[j][0] = sB[swz(kk + tg,     n)];
                bf[j][1] = sB[swz(kk + tg + 4, n)];
            }
#pragma unroll
            for (int i = 0; i < 4; i++)
#pragma unroll
                for (int j = 0; j < 8; j++)
                    mma_tf32(acc[i][j], af[i], bf[j]);
        }

        if (t + 1 < nTiles) {
            unsigned* dA = As[cur ^ 1];
            unsigned* dB = Bs[cur ^ 1];
#pragma unroll
            for (int i = 0; i < 4; i++) {
                int r = sr + i * 32;
                int mo = (r + 8 * (sc >> 2)) & 127;
                float va[4] = {ra[i].x, ra[i].y, ra[i].z, ra[i].w};
                float vb[4] = {rb[i].x, rb[i].y, rb[i].z, rb[i].w};
#pragma unroll
                for (int u = 0; u < 4; u++) {
                    dA[(sc + u) * 136 + mo] = f2tf(va[u]);
                    dB[(sc + u) * 136 + mo] = f2tf(vb[u]);
                }
            }
        }
        __syncthreads();
    }

    // epilogue
#pragma unroll
    for (int i = 0; i < 4; i++) {
        int row0 = m0 + wm + i * 16 + g;
#pragma unroll
        for (int j = 0; j < 8; j++) {
            int col = n0 + wn + j * 8 + tg * 2;
#pragma unroll
            for (int half = 0; half < 2; half++) {
                int row = row0 + half * 8;
#pragma unroll
                for (int cc = 0; cc < 2; cc++) {
                    float v = acc[i][j][half * 2 + cc];
                    int  cl = col + cc;
                    if (EPI == 1)      v = gate[cl] * v + res[(size_t)row * N + cl];
                    else if (EPI == 2) v = gelu_tanh(v + bias[cl]);
                    else if (EPI == 3) v = gate[cl] * (v + bias[cl]) + res[(size_t)row * N + cl];
                    C[(size_t)row * N + cl] = v;
                }
            }
        }
    }
}

// ---------------------------------------------------------------------------
// RoPE (q, k, v) + head-major transpose
// ---------------------------------------------------------------------------
__global__ void rope_kernel(const float* __restrict__ cosT,
                            const float* __restrict__ sinT) {
    int idx = blockIdx.x * blockDim.x + threadIdx.x;
    if (idx >= S_TOK * H_HEADS * 32) return;
    int hd2 = idx & 31;
    int h   = (idx >> 5) & (H_HEADS - 1);
    int s   = idx >> 9;
    int p   = s & (N_TOK - 1);
    float cs = cosT[p * 32 + hd2];
    float sn = sinT[p * 32 + hd2];
    const float* src = g_qkv + (size_t)s * 3 * D_MODEL + h * HD;
#pragma unroll
    for (int qi = 0; qi < 3; qi++) {
        float x1 = src[qi * D_MODEL + hd2];
        float x2 = src[qi * D_MODEL + hd2 + 32];
        float o1 = x1 * cs - x2 * sn;
        float o2 = x2 * cs + x1 * sn;
        float* dst = (qi == 0 ? g_Q : qi == 1 ? g_K : g_V)
                   + ((size_t)h * S_TOK + s) * HD;
        dst[hd2]      = o1;
        dst[hd2 + 32] = o2;
    }
}

// ---------------------------------------------------------------------------
// Block-diffusion attention, 32-key tiles, conflict-free padded smem.
//   qb < 64 (noisy):  keys [qb*16, qb*16+16)  U  [1024, 1024 + qb*16)
//   qb >= 64 (clean): keys [1024, 1024 + (qb-63)*16)
// ---------------------------------------------------------------------------
#define KP 68   // padded row stride (floats), 16B aligned

__global__ void __launch_bounds__(128)
attn_kernel(float* __restrict__ O) {
    int qb = blockIdx.x;
    int h  = blockIdx.y;
    int t  = threadIdx.x;
    int qi = t >> 3;
    int r8 = t & 7;

    __shared__ float Qs[16][KP];
    __shared__ float Ks[32][KP];
    __shared__ float Vs[32][KP];
    __shared__ float Ssc[16][32];
    __shared__ float Mrow[16], Lrow[16], Sfac[16];

    const float* Qh = g_Q + (size_t)h * S_TOK * HD;
    const float* Kh = g_K + (size_t)h * S_TOK * HD;
    const float* Vh = g_V + (size_t)h * S_TOK * HD;
    int q0 = qb * 16;

    // load Q (16 x 64) scaled
#pragma unroll
    for (int i = 0; i < 2; i++) {
        int id = t + i * 128;          // 256 float4 slots
        int row = id >> 4, c = (id & 15) * 4;
        float4 qv = *(const float4*)&Qh[(size_t)(q0 + row) * HD + c];
        qv.x *= 0.125f; qv.y *= 0.125f; qv.z *= 0.125f; qv.w *= 0.125f;
        *(float4*)&Qs[row][c] = qv;
    }
    if (t < 16) { Mrow[t] = -INFINITY; Lrow[t] = 0.f; }
    __syncthreads();

    float4 qv[16];
#pragma unroll
    for (int d4 = 0; d4 < 16; d4++) qv[d4] = *(const float4*)&Qs[qi][d4 * 4];

    float Oacc[8] = {};

    int rA0, rA1, rB0, rB1;
    if (qb < 64) { rA0 = q0;    rA1 = q0 + 16;              rB0 = N_TOK; rB1 = N_TOK + qb * 16; }
    else         { rA0 = N_TOK; rA1 = N_TOK + (qb - 63) * 16; rB0 = 0;   rB1 = 0; }

#pragma unroll 1
    for (int rng = 0; rng < 2; rng++) {
        int r0 = (rng == 0) ? rA0 : rB0;
        int r1 = (rng == 0) ? rA1 : rB1;
#pragma unroll 1
        for (int k0 = r0; k0 < r1; k0 += 32) {
            int nv = min(32, r1 - k0);
            __syncthreads();
            // load 32 K rows + 32 V rows (float4, clamped)
#pragma unroll
            for (int i = 0; i < 4; i++) {
                int id = t + i * 128;          // 512 float4 slots
                int row = id >> 4, c = (id & 15) * 4;
                int src = min(k0 + row, S_TOK - 1);
                *(float4*)&Ks[row][c] = *(const float4*)&Kh[(size_t)src * HD + c];
                *(float4*)&Vs[row][c] = *(const float4*)&Vh[(size_t)src * HD + c];
            }
            __syncthreads();

            // scores: this thread -> row qi, keys r8 + {0,8,16,24}
            float s[4] = {};
#pragma unroll
            for (int d4 = 0; d4 < 16; d4++) {
                float4 q = qv[d4];
#pragma unroll
                for (int u = 0; u < 4; u++) {
                    float4 kf = *(const float4*)&Ks[r8 + 8 * u][d4 * 4];
                    s[u] += q.x * kf.x + q.y * kf.y + q.z * kf.z + q.w * kf.w;
                }
            }
#pragma unroll
            for (int u = 0; u < 4; u++) {
                int j = r8 + 8 * u;
                Ssc[qi][j] = (j < nv) ? s[u] : -INFINITY;
            }
            __syncthreads();

            if (t < 16) {
                float m = Mrow[t];
                float cmax = m;
#pragma unroll
                for (int j = 0; j < 32; j++) cmax = fmaxf(cmax, Ssc[t][j]);
                float corr = __expf(m - cmax);
                float l = Lrow[t] * corr;
#pragma unroll
                for (int j = 0; j < 32; j++) {
                    float p = __expf(Ssc[t][j] - cmax);
                    Ssc[t][j] = p;
                    l += p;
                }
                Mrow[t] = cmax; Lrow[t] = l; Sfac[t] = corr;
            }
            __syncthreads();

            float corr = Sfac[qi];
#pragma unroll
            for (int i = 0; i < 8; i++) Oacc[i] *= corr;
#pragma unroll
            for (int j = 0; j < 32; j++) {
                float p = Ssc[qi][j];
                float4 v0 = *(const float4*)&Vs[j][r8 * 8];
                float4 v1 = *(const float4*)&Vs[j][r8 * 8 + 4];
                Oacc[0] += p * v0.x; Oacc[1] += p * v0.y;
                Oacc[2] += p * v0.z; Oacc[3] += p * v0.w;
                Oacc[4] += p * v1.x; Oacc[5] += p * v1.y;
                Oacc[6] += p * v1.z; Oacc[7] += p * v1.w;
            }
        }
    }

    float invl = 1.f / Lrow[qi];
    int row = q0 + qi;
#pragma unroll
    for (int i = 0; i < 8; i++)
        O[(size_t)row * D_MODEL + h * HD + r8 * 8 + i] = Oacc[i] * invl;
}

// ---------------------------------------------------------------------------
// kernel_launch
// ---------------------------------------------------------------------------
extern "C" void kernel_launch(void* const* d_in, const int* in_sizes, int n_in,
                              void* d_out, int out_size) {
    const float* x          = (const float*)d_in[0];
    const float* c          = (const float*)d_in[1];
    const float* cosT       = (const float*)d_in[2];
    const float* sinT       = (const float*)d_in[3];
    const float* norm1_w    = (const float*)d_in[4];
    const float* qkv_w      = (const float*)d_in[5];
    const float* attn_out_w = (const float*)d_in[6];
    const float* norm2_w    = (const float*)d_in[7];
    const float* mlp_w1     = (const float*)d_in[8];
    const float* mlp_b1     = (const float*)d_in[9];
    const float* mlp_w2     = (const float*)d_in[10];
    const float* mlp_b2     = (const float*)d_in[11];
    const float* adaLN_w    = (const float*)d_in[12];
    const float* adaLN_b    = (const float*)d_in[13];
    float* out = (float*)d_out;

    float *mods, *h, *Obuf, *x2, *h2, *m1, *qkv;
    cudaGetSymbolAddress((void**)&mods, g_mods);
    cudaGetSymbolAddress((void**)&h,    g_h);
    cudaGetSymbolAddress((void**)&qkv,  g_qkv);
    cudaGetSymbolAddress((void**)&Obuf, g_O);
    cudaGetSymbolAddress((void**)&x2,   g_x2);
    cudaGetSymbolAddress((void**)&h2,   g_h2);
    cudaGetSymbolAddress((void**)&m1,   g_m1);

    const float* sh_msa = mods + 0 * D_MODEL;
    const float* sc_msa = mods + 1 * D_MODEL;
    const float* g_msa  = mods + 2 * D_MODEL;
    const float* sh_mlp = mods + 3 * D_MODEL;
    const float* sc_mlp = mods + 4 * D_MODEL;
    const float* g_mlp  = mods + 5 * D_MODEL;

    adaln_kernel<<<(6 * D_MODEL + 127) / 128, 128>>>(c, adaLN_w, adaLN_b);

    ln_mod_kernel<<<S_TOK, 256>>>(x, norm1_w, sc_msa, sh_msa, h);

    gemm_tc<0><<<dim3(3 * D_MODEL / 128, S_TOK / 128), 128>>>(
        h, qkv_w, qkv, S_TOK, 3 * D_MODEL, D_MODEL, nullptr, nullptr, nullptr);

    rope_kernel<<<(S_TOK * H_HEADS * 32 + 255) / 256, 256>>>(cosT, sinT);

    attn_kernel<<<dim3(S_TOK / 16, H_HEADS), 128>>>(Obuf);

    gemm_tc<1><<<dim3(D_MODEL / 128, S_TOK / 128), 128>>>(
        Obuf, attn_out_w, x2, S_TOK, D_MODEL, D_MODEL, nullptr, g_msa, x);

    ln_mod_kernel<<<S_TOK, 256>>>(x2, norm2_w, sc_mlp, sh_mlp, h2);

    gemm_tc<2><<<dim3(D_MLP / 128, S_TOK / 128), 128>>>(
        h2, mlp_w1, m1, S_TOK, D_MLP, D_MODEL, mlp_b1, nullptr, nullptr);

    gemm_tc<3><<<dim3(D_MODEL / 128, S_TOK / 128), 128>>>(
        m1, mlp_w2, out, S_TOK, D_MODEL, D_MLP, mlp_b2, g_mlp, x2);
}

// round 5
// speedup vs baseline: 3.3666x; 1.2582x over previous
#include <cuda_runtime.h>
#include <cuda_bf16.h>
#include <cuda_fp16.h>
#include <math.h>

// ---------------------------------------------------------------------------
// Problem constants
// ---------------------------------------------------------------------------
#define S_TOK   2048
#define N_TOK   1024
#define D_MODEL 1024
#define H_HEADS 16
#define HD      64
#define D_MLP   4096
#define COND    128
#define BSZ     16

// ---------------------------------------------------------------------------
// Device scratch
// ---------------------------------------------------------------------------
__device__ float g_mods[6 * D_MODEL];
__device__ float g_h   [S_TOK * D_MODEL];
__device__ float g_qkv [S_TOK * 3 * D_MODEL];
__device__ float g_Q   [H_HEADS * S_TOK * HD];
__device__ float g_K   [H_HEADS * S_TOK * HD];
__device__ float g_V   [H_HEADS * S_TOK * HD];
__device__ float g_O   [S_TOK * D_MODEL];
__device__ float g_x2  [S_TOK * D_MODEL];
__device__ float g_h2  [S_TOK * D_MODEL];
__device__ float g_m1  [S_TOK * D_MLP];

// ---------------------------------------------------------------------------
// adaLN
// ---------------------------------------------------------------------------
__global__ void adaln_kernel(const float* __restrict__ c,
                             const float* __restrict__ W,
                             const float* __restrict__ b) {
    __shared__ float cs[COND];
    int tid = threadIdx.x;
    if (tid < COND) cs[tid] = c[tid];
    __syncthreads();
    int i = blockIdx.x * blockDim.x + tid;
    if (i >= 6 * D_MODEL) return;
    const float* w = W + (size_t)i * COND;
    float acc = 0.f;
#pragma unroll 8
    for (int j = 0; j < COND; j++) acc += w[j] * cs[j];
    g_mods[i] = acc + b[i];
}

// ---------------------------------------------------------------------------
// LayerNorm + modulate
// ---------------------------------------------------------------------------
__inline__ __device__ float warp_reduce_sum(float v) {
#pragma unroll
    for (int o = 16; o > 0; o >>= 1) v += __shfl_xor_sync(0xffffffffu, v, o);
    return v;
}

__global__ void ln_mod_kernel(const float* __restrict__ X,
                              const float* __restrict__ w,
                              const float* __restrict__ sc,
                              const float* __restrict__ sh,
                              float* __restrict__ out) {
    int row = blockIdx.x;
    const float4* x4 = (const float4*)(X + (size_t)row * D_MODEL);
    int tid = threadIdx.x;
    float4 v = x4[tid];
    float s  = v.x + v.y + v.z + v.w;
    float ss = v.x*v.x + v.y*v.y + v.z*v.z + v.w*v.w;
    __shared__ float red_s[8], red_ss[8];
    s  = warp_reduce_sum(s);
    ss = warp_reduce_sum(ss);
    int wid = tid >> 5, lid = tid & 31;
    if (lid == 0) { red_s[wid] = s; red_ss[wid] = ss; }
    __syncthreads();
    if (wid == 0) {
        float a = (lid < 8) ? red_s[lid]  : 0.f;
        float b = (lid < 8) ? red_ss[lid] : 0.f;
        a = warp_reduce_sum(a);
        b = warp_reduce_sum(b);
        if (lid == 0) { red_s[0] = a; red_ss[0] = b; }
    }
    __syncthreads();
    float mu  = red_s[0] * (1.f / D_MODEL);
    float var = red_ss[0] * (1.f / D_MODEL) - mu * mu;
    float inv = rsqrtf(var + 1e-5f);
    int d0 = tid * 4;
    float* o = out + (size_t)row * D_MODEL;
    float vv[4] = {v.x, v.y, v.z, v.w};
#pragma unroll
    for (int i = 0; i < 4; i++) {
        int d = d0 + i;
        o[d] = (vv[i] - mu) * inv * w[d] * (1.f + sc[d]) + sh[d];
    }
}

// ---------------------------------------------------------------------------
// FP16 tensor-core GEMM: C[M,N] = A[M,K] @ W[N,K]^T (+ epilogue)
// Each 32-bit smem word = half2 (k-pair). Fragment word-index pattern for
// m16n8k16.f16 is identical to m16n8k8.tf32, so layout/swizzle carry over;
// a 16-word k-tile now covers 32 k values.
// CTA 128x128, 4 warps (2x2) each 64x64, double-buffered smem.
// EPI: 0 none, 1 gate*acc+res, 2 gelu(acc+bias), 3 gate*(acc+bias)+res
// ---------------------------------------------------------------------------
__device__ __forceinline__ float gelu_tanh(float x) {
    float x3 = x * x * x;
    return 0.5f * x * (1.f + tanhf(0.7978845608028654f * (x + 0.044715f * x3)));
}

__device__ __forceinline__ unsigned pack_h2(float x, float y) {
    __half2 h = __floats2half2_rn(x, y);
    return *(unsigned*)&h;
}

__device__ __forceinline__ int swz(int k, int m) {
    return k * 136 + ((m + ((k >> 2) << 3)) & 127);
}

__device__ __forceinline__ void mma_fp16(float* c, const unsigned* a, const unsigned* b) {
    asm volatile(
        "mma.sync.aligned.m16n8k16.row.col.f32.f16.f16.f32 "
        "{%0,%1,%2,%3}, {%4,%5,%6,%7}, {%8,%9}, {%0,%1,%2,%3};\n"
        : "+f"(c[0]), "+f"(c[1]), "+f"(c[2]), "+f"(c[3])
        : "r"(a[0]), "r"(a[1]), "r"(a[2]), "r"(a[3]), "r"(b[0]), "r"(b[1]));
}

template<int EPI>
__global__ void __launch_bounds__(128, 2)
gemm_tc(const float* __restrict__ A, const float* __restrict__ W,
        float* __restrict__ C, int M, int N, int K,
        const float* __restrict__ bias,
        const float* __restrict__ gate,
        const float* __restrict__ res) {
    __shared__ unsigned As[2][16 * 136];
    __shared__ unsigned Bs[2][16 * 136];

    const int m0 = blockIdx.y * 128;
    const int n0 = blockIdx.x * 128;
    const int tid = threadIdx.x;
    const int lane = tid & 31;
    const int warp = tid >> 5;
    const int wm = (warp >> 1) * 64;
    const int wn = (warp & 1) * 64;
    const int g  = lane >> 2;
    const int tg = lane & 3;

    const int sr = tid >> 2;          // 0..31
    const int sc = (tid & 3) * 4;     // word col 0,4,8,12
    const int kf = sc * 2;            // k-float offset 0,8,16,24

    float acc[4][8][4] = {};
    float4 ra[4][2], rb[4][2];

    const int nTiles = K / 32;        // 32 k per tile

    // prologue: load tile 0 (8 floats per row per operand)
#pragma unroll
    for (int i = 0; i < 4; i++) {
        int r = sr + i * 32;
        ra[i][0] = *(const float4*)&A[(size_t)(m0 + r) * K + kf];
        ra[i][1] = *(const float4*)&A[(size_t)(m0 + r) * K + kf + 4];
        rb[i][0] = *(const float4*)&W[(size_t)(n0 + r) * K + kf];
        rb[i][1] = *(const float4*)&W[(size_t)(n0 + r) * K + kf + 4];
    }
    {
        unsigned* sA = As[0];
        unsigned* sB = Bs[0];
#pragma unroll
        for (int i = 0; i < 4; i++) {
            int r = sr + i * 32;
            int mo = (r + 8 * (tid & 3)) & 127;
            sA[(sc + 0) * 136 + mo] = pack_h2(ra[i][0].x, ra[i][0].y);
            sA[(sc + 1) * 136 + mo] = pack_h2(ra[i][0].z, ra[i][0].w);
            sA[(sc + 2) * 136 + mo] = pack_h2(ra[i][1].x, ra[i][1].y);
            sA[(sc + 3) * 136 + mo] = pack_h2(ra[i][1].z, ra[i][1].w);
            sB[(sc + 0) * 136 + mo] = pack_h2(rb[i][0].x, rb[i][0].y);
            sB[(sc + 1) * 136 + mo] = pack_h2(rb[i][0].z, rb[i][0].w);
            sB[(sc + 2) * 136 + mo] = pack_h2(rb[i][1].x, rb[i][1].y);
            sB[(sc + 3) * 136 + mo] = pack_h2(rb[i][1].z, rb[i][1].w);
        }
    }
    __syncthreads();

    for (int t = 0; t < nTiles; t++) {
        int cur = t & 1;
        if (t + 1 < nTiles) {
            int k0 = (t + 1) * 32;
#pragma unroll
            for (int i = 0; i < 4; i++) {
                int r = sr + i * 32;
                ra[i][0] = *(const float4*)&A[(size_t)(m0 + r) * K + k0 + kf];
                ra[i][1] = *(const float4*)&A[(size_t)(m0 + r) * K + k0 + kf + 4];
                rb[i][0] = *(const float4*)&W[(size_t)(n0 + r) * K + k0 + kf];
                rb[i][1] = *(const float4*)&W[(size_t)(n0 + r) * K + k0 + kf + 4];
            }
        }

        const unsigned* sA = As[cur];
        const unsigned* sB = Bs[cur];
#pragma unroll
        for (int kk = 0; kk < 16; kk += 8) {
            unsigned af[4][4], bf[8][2];
#pragma unroll
            for (int i = 0; i < 4; i++) {
                int m = wm + i * 16 + g;
                af[i][0] = sA[swz(kk + tg,     m)];
                af[i][1] = sA[swz(kk + tg,     m + 8)];
                af[i][2] = sA[swz(kk + tg + 4, m)];
                af[i][3] = sA[swz(kk + tg + 4, m + 8)];
            }
#pragma unroll
            for (int j = 0; j < 8; j++) {
                int n = wn + j * 8 + g;
                bf[j][0] = sB[swz(kk + tg,     n)];
                bf[j][1] = sB[swz(kk + tg + 4, n)];
            }
#pragma unroll
            for (int i = 0; i < 4; i++)
#pragma unroll
                for (int j = 0; j < 8; j++)
                    mma_fp16(acc[i][j], af[i], bf[j]);
        }

        if (t + 1 < nTiles) {
            unsigned* dA = As[cur ^ 1];
            unsigned* dB = Bs[cur ^ 1];
#pragma unroll
            for (int i = 0; i < 4; i++) {
                int r = sr + i * 32;
                int mo = (r + 8 * (tid & 3)) & 127;
                dA[(sc + 0) * 136 + mo] = pack_h2(ra[i][0].x, ra[i][0].y);
                dA[(sc + 1) * 136 + mo] = pack_h2(ra[i][0].z, ra[i][0].w);
                dA[(sc + 2) * 136 + mo] = pack_h2(ra[i][1].x, ra[i][1].y);
                dA[(sc + 3) * 136 + mo] = pack_h2(ra[i][1].z, ra[i][1].w);
                dB[(sc + 0) * 136 + mo] = pack_h2(rb[i][0].x, rb[i][0].y);
                dB[(sc + 1) * 136 + mo] = pack_h2(rb[i][0].z, rb[i][0].w);
                dB[(sc + 2) * 136 + mo] = pack_h2(rb[i][1].x, rb[i][1].y);
                dB[(sc + 3) * 136 + mo] = pack_h2(rb[i][1].z, rb[i][1].w);
            }
        }
        __syncthreads();
    }

    // epilogue (C fragment layout identical to tf32 m16n8k8)
#pragma unroll
    for (int i = 0; i < 4; i++) {
        int row0 = m0 + wm + i * 16 + g;
#pragma unroll
        for (int j = 0; j < 8; j++) {
            int col = n0 + wn + j * 8 + tg * 2;
#pragma unroll
            for (int half = 0; half < 2; half++) {
                int row = row0 + half * 8;
#pragma unroll
                for (int cc = 0; cc < 2; cc++) {
                    float v = acc[i][j][half * 2 + cc];
                    int  cl = col + cc;
                    if (EPI == 1)      v = gate[cl] * v + res[(size_t)row * N + cl];
                    else if (EPI == 2) v = gelu_tanh(v + bias[cl]);
                    else if (EPI == 3) v = gate[cl] * (v + bias[cl]) + res[(size_t)row * N + cl];
                    C[(size_t)row * N + cl] = v;
                }
            }
        }
    }
}

// ---------------------------------------------------------------------------
// RoPE (q, k, v) + head-major transpose
// ---------------------------------------------------------------------------
__global__ void rope_kernel(const float* __restrict__ cosT,
                            const float* __restrict__ sinT) {
    int idx = blockIdx.x * blockDim.x + threadIdx.x;
    if (idx >= S_TOK * H_HEADS * 32) return;
    int hd2 = idx & 31;
    int h   = (idx >> 5) & (H_HEADS - 1);
    int s   = idx >> 9;
    int p   = s & (N_TOK - 1);
    float cs = cosT[p * 32 + hd2];
    float sn = sinT[p * 32 + hd2];
    const float* src = g_qkv + (size_t)s * 3 * D_MODEL + h * HD;
#pragma unroll
    for (int qi = 0; qi < 3; qi++) {
        float x1 = src[qi * D_MODEL + hd2];
        float x2 = src[qi * D_MODEL + hd2 + 32];
        float o1 = x1 * cs - x2 * sn;
        float o2 = x2 * cs + x1 * sn;
        float* dst = (qi == 0 ? g_Q : qi == 1 ? g_K : g_V)
                   + ((size_t)h * S_TOK + s) * HD;
        dst[hd2]      = o1;
        dst[hd2 + 32] = o2;
    }
}

// ---------------------------------------------------------------------------
// Block-diffusion attention, 64-key tiles, shfl softmax (no serial section).
//   qb < 64 (noisy):  keys [qb*16, qb*16+16)  U  [1024, 1024 + qb*16)
//   qb >= 64 (clean): keys [1024, 1024 + (qb-63)*16)
// 128 threads: thread t -> (qi = t>>3, r8 = t&7); row's 8 threads are
// consecutive lanes of one warp -> softmax reduced with 3 shfl_xor steps.
// ---------------------------------------------------------------------------
#define AP 68   // padded row stride (floats)

__global__ void __launch_bounds__(128)
attn_kernel(float* __restrict__ O) {
    int qb = blockIdx.x;
    int h  = blockIdx.y;
    int t  = threadIdx.x;
    int qi = t >> 3;
    int r8 = t & 7;

    __shared__ float Qs[16][AP];
    __shared__ float Ks[64][AP];
    __shared__ float Vs[64][AP];
    __shared__ float Ps[16][AP];

    const float* Qh = g_Q + (size_t)h * S_TOK * HD;
    const float* Kh = g_K + (size_t)h * S_TOK * HD;
    const float* Vh = g_V + (size_t)h * S_TOK * HD;
    int q0 = qb * 16;

    // load Q (16 x 64) scaled by 1/sqrt(64)
#pragma unroll
    for (int i = 0; i < 2; i++) {
        int id = t + i * 128;
        int row = id >> 4, c = (id & 15) * 4;
        float4 qv4 = *(const float4*)&Qh[(size_t)(q0 + row) * HD + c];
        qv4.x *= 0.125f; qv4.y *= 0.125f; qv4.z *= 0.125f; qv4.w *= 0.125f;
        *(float4*)&Qs[row][c] = qv4;
    }
    __syncthreads();

    float4 qv[16];
#pragma unroll
    for (int d4 = 0; d4 < 16; d4++) qv[d4] = *(const float4*)&Qs[qi][d4 * 4];

    float Oacc[8] = {};
    float mrun = -INFINITY, lrun = 0.f;

    int rA0, rA1, rB0, rB1;
    if (qb < 64) { rA0 = q0;    rA1 = q0 + 16;                rB0 = N_TOK; rB1 = N_TOK + qb * 16; }
    else         { rA0 = N_TOK; rA1 = N_TOK + (qb - 63) * 16; rB0 = 0;     rB1 = 0; }

#pragma unroll 1
    for (int rng = 0; rng < 2; rng++) {
        int r0 = (rng == 0) ? rA0 : rB0;
        int r1 = (rng == 0) ? rA1 : rB1;
#pragma unroll 1
        for (int k0 = r0; k0 < r1; k0 += 64) {
            int nv = min(64, r1 - k0);
            __syncthreads();
            // load 64 K rows + 64 V rows
#pragma unroll
            for (int i = 0; i < 8; i++) {
                int id = t + i * 128;
                int row = id >> 4, c = (id & 15) * 4;
                int src = min(k0 + row, S_TOK - 1);
                *(float4*)&Ks[row][c] = *(const float4*)&Kh[(size_t)src * HD + c];
                *(float4*)&Vs[row][c] = *(const float4*)&Vh[(size_t)src * HD + c];
            }
            __syncthreads();

            // scores: keys r8 + 8u, u in [0,8)
            float s[8];
#pragma unroll
            for (int u = 0; u < 8; u++) s[u] = 0.f;
#pragma unroll
            for (int d4 = 0; d4 < 16; d4++) {
                float4 q = qv[d4];
#pragma unroll
                for (int u = 0; u < 8; u++) {
                    float4 kf = *(const float4*)&Ks[r8 + 8 * u][d4 * 4];
                    s[u] += q.x * kf.x + q.y * kf.y + q.z * kf.z + q.w * kf.w;
                }
            }
#pragma unroll
            for (int u = 0; u < 8; u++)
                if (r8 + 8 * u >= nv) s[u] = -INFINITY;

            // row max across 8 lanes
            float tmax = s[0];
#pragma unroll
            for (int u = 1; u < 8; u++) tmax = fmaxf(tmax, s[u]);
            tmax = fmaxf(tmax, __shfl_xor_sync(0xffffffffu, tmax, 1));
            tmax = fmaxf(tmax, __shfl_xor_sync(0xffffffffu, tmax, 2));
            tmax = fmaxf(tmax, __shfl_xor_sync(0xffffffffu, tmax, 4));

            float newm = fmaxf(mrun, tmax);
            float corr = __expf(mrun - newm);
            float tsum = 0.f;
#pragma unroll
            for (int u = 0; u < 8; u++) {
                float p = __expf(s[u] - newm);
                s[u] = p;
                tsum += p;
            }
            tsum += __shfl_xor_sync(0xffffffffu, tsum, 1);
            tsum += __shfl_xor_sync(0xffffffffu, tsum, 2);
            tsum += __shfl_xor_sync(0xffffffffu, tsum, 4);
            lrun = lrun * corr + tsum;
            mrun = newm;

#pragma unroll
            for (int u = 0; u < 8; u++) Ps[qi][r8 + 8 * u] = s[u];
#pragma unroll
            for (int i = 0; i < 8; i++) Oacc[i] *= corr;
            __syncthreads();

            // PV accumulation: this thread owns dims r8*8 .. r8*8+7 of row qi
#pragma unroll 4
            for (int j = 0; j < 64; j++) {
                float p = Ps[qi][j];
                float4 v0 = *(const float4*)&Vs[j][r8 * 8];
                float4 v1 = *(const float4*)&Vs[j][r8 * 8 + 4];
                Oacc[0] += p * v0.x; Oacc[1] += p * v0.y;
                Oacc[2] += p * v0.z; Oacc[3] += p * v0.w;
                Oacc[4] += p * v1.x; Oacc[5] += p * v1.y;
                Oacc[6] += p * v1.z; Oacc[7] += p * v1.w;
            }
        }
    }

    float invl = 1.f / lrun;
    int row = q0 + qi;
    float4 o0 = make_float4(Oacc[0]*invl, Oacc[1]*invl, Oacc[2]*invl, Oacc[3]*invl);
    float4 o1 = make_float4(Oacc[4]*invl, Oacc[5]*invl, Oacc[6]*invl, Oacc[7]*invl);
    *(float4*)&O[(size_t)row * D_MODEL + h * HD + r8 * 8]     = o0;
    *(float4*)&O[(size_t)row * D_MODEL + h * HD + r8 * 8 + 4] = o1;
}

// ---------------------------------------------------------------------------
// kernel_launch
// ---------------------------------------------------------------------------
extern "C" void kernel_launch(void* const* d_in, const int* in_sizes, int n_in,
                              void* d_out, int out_size) {
    const float* x          = (const float*)d_in[0];
    const float* c          = (const float*)d_in[1];
    const float* cosT       = (const float*)d_in[2];
    const float* sinT       = (const float*)d_in[3];
    const float* norm1_w    = (const float*)d_in[4];
    const float* qkv_w      = (const float*)d_in[5];
    const float* attn_out_w = (const float*)d_in[6];
    const float* norm2_w    = (const float*)d_in[7];
    const float* mlp_w1     = (const float*)d_in[8];
    const float* mlp_b1     = (const float*)d_in[9];
    const float* mlp_w2     = (const float*)d_in[10];
    const float* mlp_b2     = (const float*)d_in[11];
    const float* adaLN_w    = (const float*)d_in[12];
    const float* adaLN_b    = (const float*)d_in[13];
    float* out = (float*)d_out;

    float *mods, *h, *Obuf, *x2, *h2, *m1, *qkv;
    cudaGetSymbolAddress((void**)&mods, g_mods);
    cudaGetSymbolAddress((void**)&h,    g_h);
    cudaGetSymbolAddress((void**)&qkv,  g_qkv);
    cudaGetSymbolAddress((void**)&Obuf, g_O);
    cudaGetSymbolAddress((void**)&x2,   g_x2);
    cudaGetSymbolAddress((void**)&h2,   g_h2);
    cudaGetSymbolAddress((void**)&m1,   g_m1);

    const float* sh_msa = mods + 0 * D_MODEL;
    const float* sc_msa = mods + 1 * D_MODEL;
    const float* g_msa  = mods + 2 * D_MODEL;
    const float* sh_mlp = mods + 3 * D_MODEL;
    const float* sc_mlp = mods + 4 * D_MODEL;
    const float* g_mlp  = mods + 5 * D_MODEL;

    adaln_kernel<<<(6 * D_MODEL + 127) / 128, 128>>>(c, adaLN_w, adaLN_b);

    ln_mod_kernel<<<S_TOK, 256>>>(x, norm1_w, sc_msa, sh_msa, h);

    gemm_tc<0><<<dim3(3 * D_MODEL / 128, S_TOK / 128), 128>>>(
        h, qkv_w, qkv, S_TOK, 3 * D_MODEL, D_MODEL, nullptr, nullptr, nullptr);

    rope_kernel<<<(S_TOK * H_HEADS * 32 + 255) / 256, 256>>>(cosT, sinT);

    attn_kernel<<<dim3(S_TOK / 16, H_HEADS), 128>>>(Obuf);

    gemm_tc<1><<<dim3(D_MODEL / 128, S_TOK / 128), 128>>>(
        Obuf, attn_out_w, x2, S_TOK, D_MODEL, D_MODEL, nullptr, g_msa, x);

    ln_mod_kernel<<<S_TOK, 256>>>(x2, norm2_w, sc_mlp, sh_mlp, h2);

    gemm_tc<2><<<dim3(D_MLP / 128, S_TOK / 128), 128>>>(
        h2, mlp_w1, m1, S_TOK, D_MLP, D_MODEL, mlp_b1, nullptr, nullptr);

    gemm_tc<3><<<dim3(D_MODEL / 128, S_TOK / 128), 128>>>(
        m1, mlp_w2, out, S_TOK, D_MODEL, D_MLP, mlp_b2, g_mlp, x2);
}

// round 6
// speedup vs baseline: 3.8236x; 1.1358x over previous
#include <cuda_runtime.h>
#include <cuda_bf16.h>
#include <cuda_fp16.h>
#include <math.h>

// ---------------------------------------------------------------------------
// Problem constants
// ---------------------------------------------------------------------------
#define S_TOK   2048
#define N_TOK   1024
#define D_MODEL 1024
#define H_HEADS 16
#define HD      64
#define D_MLP   4096
#define COND    128
#define BSZ     16

// ---------------------------------------------------------------------------
// Device scratch
// ---------------------------------------------------------------------------
__device__ float  g_mods[6 * D_MODEL];
__device__ __half g_h  [S_TOK * D_MODEL];
__device__ __half g_h2 [S_TOK * D_MODEL];
__device__ __half g_Oh [S_TOK * D_MODEL];
__device__ __half g_m1 [S_TOK * D_MLP];
__device__ float  g_Q  [H_HEADS * S_TOK * HD];
__device__ float  g_K  [H_HEADS * S_TOK * HD];
__device__ float  g_V  [H_HEADS * S_TOK * HD];
__device__ float  g_x2 [S_TOK * D_MODEL];
// fp16 weights (converted once per launch)
__device__ __half g_wq [3 * D_MODEL * D_MODEL];
__device__ __half g_wo [D_MODEL * D_MODEL];
__device__ __half g_w1 [D_MLP * D_MODEL];
__device__ __half g_w2 [D_MODEL * D_MLP];

// ---------------------------------------------------------------------------
// fp32 -> fp16 convert (vectorized)
// ---------------------------------------------------------------------------
__global__ void f2h_kernel(const float* __restrict__ src, __half* __restrict__ dst, int n4) {
    int i = blockIdx.x * blockDim.x + threadIdx.x;
    if (i >= n4) return;
    float4 v = ((const float4*)src)[i];
    __half2 h0 = __floats2half2_rn(v.x, v.y);
    __half2 h1 = __floats2half2_rn(v.z, v.w);
    ((__half2*)dst)[2 * i]     = h0;
    ((__half2*)dst)[2 * i + 1] = h1;
}

// ---------------------------------------------------------------------------
// adaLN
// ---------------------------------------------------------------------------
__global__ void adaln_kernel(const float* __restrict__ c,
                             const float* __restrict__ W,
                             const float* __restrict__ b) {
    __shared__ float cs[COND];
    int tid = threadIdx.x;
    if (tid < COND) cs[tid] = c[tid];
    __syncthreads();
    int i = blockIdx.x * blockDim.x + tid;
    if (i >= 6 * D_MODEL) return;
    const float* w = W + (size_t)i * COND;
    float acc = 0.f;
#pragma unroll 8
    for (int j = 0; j < COND; j++) acc += w[j] * cs[j];
    g_mods[i] = acc + b[i];
}

// ---------------------------------------------------------------------------
// LayerNorm + modulate -> fp16 output
// ---------------------------------------------------------------------------
__inline__ __device__ float warp_reduce_sum(float v) {
#pragma unroll
    for (int o = 16; o > 0; o >>= 1) v += __shfl_xor_sync(0xffffffffu, v, o);
    return v;
}

__global__ void ln_mod_kernel(const float* __restrict__ X,
                              const float* __restrict__ w,
                              const float* __restrict__ sc,
                              const float* __restrict__ sh,
                              __half* __restrict__ out) {
    int row = blockIdx.x;
    const float4* x4 = (const float4*)(X + (size_t)row * D_MODEL);
    int tid = threadIdx.x;
    float4 v = x4[tid];
    float s  = v.x + v.y + v.z + v.w;
    float ss = v.x*v.x + v.y*v.y + v.z*v.z + v.w*v.w;
    __shared__ float red_s[8], red_ss[8];
    s  = warp_reduce_sum(s);
    ss = warp_reduce_sum(ss);
    int wid = tid >> 5, lid = tid & 31;
    if (lid == 0) { red_s[wid] = s; red_ss[wid] = ss; }
    __syncthreads();
    if (wid == 0) {
        float a = (lid < 8) ? red_s[lid]  : 0.f;
        float b = (lid < 8) ? red_ss[lid] : 0.f;
        a = warp_reduce_sum(a);
        b = warp_reduce_sum(b);
        if (lid == 0) { red_s[0] = a; red_ss[0] = b; }
    }
    __syncthreads();
    float mu  = red_s[0] * (1.f / D_MODEL);
    float var = red_ss[0] * (1.f / D_MODEL) - mu * mu;
    float inv = rsqrtf(var + 1e-5f);
    int d0 = tid * 4;
    float vv[4] = {v.x, v.y, v.z, v.w};
    float o[4];
#pragma unroll
    for (int i = 0; i < 4; i++) {
        int d = d0 + i;
        o[i] = (vv[i] - mu) * inv * w[d] * (1.f + sc[d]) + sh[d];
    }
    __half2 h0 = __floats2half2_rn(o[0], o[1]);
    __half2 h1 = __floats2half2_rn(o[2], o[3]);
    *(__half2*)&out[(size_t)row * D_MODEL + d0]     = h0;
    *(__half2*)&out[(size_t)row * D_MODEL + d0 + 2] = h1;
}

// ---------------------------------------------------------------------------
// FP16 GEMM with cp.async + ldmatrix.
// A [M,K] fp16 row-major, B [N,K] fp16 row-major (= col-major k x n operand).
// smem layout: 128 rows x 32 halves (64B rows), 16B chunk swizzle:
//   chunk' = chunk ^ ((row>>1)&3)   -- conflict-free for cp.async stores and
//   all ldmatrix row-address patterns.
// CTA 128x128, 4 warps (2x2) each 64x64, double-buffered.
// EPI: 0 qkv+rope -> Q/K/V fp32, 1 gate*acc+res -> fp32,
//      2 gelu(acc+bias) -> fp16, 3 gate*(acc+bias)+res -> fp32
// ---------------------------------------------------------------------------
__device__ __forceinline__ float gelu_tanh(float x) {
    float x3 = x * x * x;
    return 0.5f * x * (1.f + tanhf(0.7978845608028654f * (x + 0.044715f * x3)));
}

__device__ __forceinline__ void cp16(void* dst, const void* src) {
    unsigned d = (unsigned)__cvta_generic_to_shared(dst);
    asm volatile("cp.async.cg.shared.global [%0], [%1], 16;\n" :: "r"(d), "l"(src));
}

__device__ __forceinline__ void ldsm4(unsigned& r0, unsigned& r1, unsigned& r2, unsigned& r3,
                                      const __half* p) {
    unsigned a = (unsigned)__cvta_generic_to_shared(p);
    asm volatile("ldmatrix.sync.aligned.m8n8.x4.shared.b16 {%0,%1,%2,%3}, [%4];\n"
                 : "=r"(r0), "=r"(r1), "=r"(r2), "=r"(r3) : "r"(a));
}

__device__ __forceinline__ void mma_fp16(float* c, const unsigned* a, const unsigned* b) {
    asm volatile(
        "mma.sync.aligned.m16n8k16.row.col.f32.f16.f16.f32 "
        "{%0,%1,%2,%3}, {%4,%5,%6,%7}, {%8,%9}, {%0,%1,%2,%3};\n"
        : "+f"(c[0]), "+f"(c[1]), "+f"(c[2]), "+f"(c[3])
        : "r"(a[0]), "r"(a[1]), "r"(a[2]), "r"(a[3]), "r"(b[0]), "r"(b[1]));
}

template<int EPI>
__global__ void __launch_bounds__(128, 2)
gemm16(const __half* __restrict__ A, const __half* __restrict__ B,
       void* __restrict__ Cout, int M, int N, int K,
       const float* __restrict__ bias, const float* __restrict__ gate,
       const float* __restrict__ res,
       const float* __restrict__ cosT, const float* __restrict__ sinT,
       float* __restrict__ Qp, float* __restrict__ Kp, float* __restrict__ Vp) {
    __shared__ __half As[2][128 * 32];
    __shared__ __half Bs[2][128 * 32];

    const int m0 = blockIdx.y * 128;
    const int n0 = blockIdx.x * 128;
    const int tid  = threadIdx.x;
    const int lane = tid & 31;
    const int warp = tid >> 5;
    const int wm = (warp >> 1) * 64;
    const int wn = (warp & 1) * 64;
    const int g  = lane >> 2;
    const int tg = lane & 3;
    const int sr  = tid >> 2;     // 0..31
    const int scn = tid & 3;      // chunk 0..3

    float acc[4][8][4] = {};
    const int nT = K / 32;

    // ldmatrix lane decomposition
    const int lrow = lane & 7;
    const int a_r8 = ((lane >> 3) & 1) * 8;
    const int a_cb = (lane >> 4) & 1;
    const int b_r8 = ((lane >> 4) & 1) * 8;
    const int b_cb = (lane >> 3) & 1;

    // issue tile k0 into buffer b
    auto issue = [&](int b, int k0) {
#pragma unroll
        for (int i = 0; i < 4; i++) {
            int r  = sr + 32 * i;
            int sw = scn ^ ((r >> 1) & 3);
            cp16(&As[b][r * 32 + sw * 8], &A[(size_t)(m0 + r) * K + k0 + scn * 8]);
            cp16(&Bs[b][r * 32 + sw * 8], &B[(size_t)(n0 + r) * K + k0 + scn * 8]);
        }
        asm volatile("cp.async.commit_group;\n");
    };

    issue(0, 0);

    for (int t = 0; t < nT; t++) {
        asm volatile("cp.async.wait_group 0;\n");
        __syncthreads();
        if (t + 1 < nT) issue((t + 1) & 1, (t + 1) * 32);

        const __half* sA = As[t & 1];
        const __half* sB = Bs[t & 1];
#pragma unroll
        for (int kk = 0; kk < 2; kk++) {
            unsigned af[4][4], bf[8][2];
#pragma unroll
            for (int i = 0; i < 4; i++) {
                int mr = wm + i * 16 + lrow + a_r8;
                int ch = 2 * kk + a_cb;
                int sw = ch ^ ((mr >> 1) & 3);
                ldsm4(af[i][0], af[i][1], af[i][2], af[i][3], &sA[mr * 32 + sw * 8]);
            }
#pragma unroll
            for (int jp = 0; jp < 4; jp++) {
                int nr = wn + jp * 16 + lrow + b_r8;
                int ch = 2 * kk + b_cb;
                int sw = ch ^ ((nr >> 1) & 3);
                ldsm4(bf[2*jp][0], bf[2*jp][1], bf[2*jp+1][0], bf[2*jp+1][1],
                      &sB[nr * 32 + sw * 8]);
            }
#pragma unroll
            for (int i = 0; i < 4; i++)
#pragma unroll
                for (int j = 0; j < 8; j++)
                    mma_fp16(acc[i][j], af[i], bf[j]);
        }
        // single barrier per iteration: the barrier at the top of the next
        // iteration orders this iteration's ldmatrix reads before the
        // cp.async writes that will overwrite this buffer (2 tiles later).
        __syncthreads();
    }

    // ---------------- epilogues ----------------
    if (EPI == 0) {
        // qkv + rope: this warp's 64-col block is exactly one (q/k/v, head)
        int colBlock = n0 + wn;
        int qidx = colBlock >> 10;
        int head = (colBlock & 1023) >> 6;
        float* dstBase = (qidx == 0 ? Qp : qidx == 1 ? Kp : Vp)
                       + (size_t)head * S_TOK * HD;
#pragma unroll
        for (int i = 0; i < 4; i++) {
#pragma unroll
            for (int hh = 0; hh < 2; hh++) {
                int row = m0 + wm + i * 16 + g + hh * 8;
                int p = row & (N_TOK - 1);
                float* dst = dstBase + (size_t)row * HD;
#pragma unroll
                for (int j = 0; j < 4; j++) {
#pragma unroll
                    for (int cc = 0; cc < 2; cc++) {
                        int d = j * 8 + tg * 2 + cc;
                        float x1 = acc[i][j][hh * 2 + cc];
                        float x2 = acc[i][j + 4][hh * 2 + cc];
                        float cs = cosT[p * 32 + d];
                        float sn = sinT[p * 32 + d];
                        dst[d]      = x1 * cs - x2 * sn;
                        dst[d + 32] = x2 * cs + x1 * sn;
                    }
                }
            }
        }
        return;
    }

#pragma unroll
    for (int i = 0; i < 4; i++) {
        int row0 = m0 + wm + i * 16 + g;
#pragma unroll
        for (int j = 0; j < 8; j++) {
            int col = n0 + wn + j * 8 + tg * 2;
#pragma unroll
            for (int hh = 0; hh < 2; hh++) {
                int row = row0 + hh * 8;
                float v0 = acc[i][j][hh * 2 + 0];
                float v1 = acc[i][j][hh * 2 + 1];
                if (EPI == 1) {
                    float* C = (float*)Cout;
                    C[(size_t)row * N + col]     = gate[col] * v0 + res[(size_t)row * N + col];
                    C[(size_t)row * N + col + 1] = gate[col+1] * v1 + res[(size_t)row * N + col + 1];
                } else if (EPI == 2) {
                    __half* C = (__half*)Cout;
                    __half2 hv = __floats2half2_rn(gelu_tanh(v0 + bias[col]),
                                                   gelu_tanh(v1 + bias[col + 1]));
                    *(__half2*)&C[(size_t)row * N + col] = hv;
                } else {
                    float* C = (float*)Cout;
                    C[(size_t)row * N + col]     = gate[col] * (v0 + bias[col]) + res[(size_t)row * N + col];
                    C[(size_t)row * N + col + 1] = gate[col+1] * (v1 + bias[col+1]) + res[(size_t)row * N + col + 1];
                }
            }
        }
    }
}

// ---------------------------------------------------------------------------
// Block-diffusion attention, 64-key tiles, shfl softmax; fp16 output.
//   qb < 64 (noisy):  keys [qb*16, qb*16+16)  U  [1024, 1024 + qb*16)
//   qb >= 64 (clean): keys [1024, 1024 + (qb-63)*16)
// ---------------------------------------------------------------------------
#define AP 68   // padded row stride (floats)

__global__ void __launch_bounds__(128)
attn_kernel(__half* __restrict__ O) {
    int qb = blockIdx.x;
    int h  = blockIdx.y;
    int t  = threadIdx.x;
    int qi = t >> 3;
    int r8 = t & 7;

    __shared__ float Qs[16][AP];
    __shared__ float Ks[64][AP];
    __shared__ float Vs[64][AP];
    __shared__ float Ps[16][AP];

    const float* Qh = g_Q + (size_t)h * S_TOK * HD;
    const float* Kh = g_K + (size_t)h * S_TOK * HD;
    const float* Vh = g_V + (size_t)h * S_TOK * HD;
    int q0 = qb * 16;

#pragma unroll
    for (int i = 0; i < 2; i++) {
        int id = t + i * 128;
        int row = id >> 4, c = (id & 15) * 4;
        float4 qv4 = *(const float4*)&Qh[(size_t)(q0 + row) * HD + c];
        qv4.x *= 0.125f; qv4.y *= 0.125f; qv4.z *= 0.125f; qv4.w *= 0.125f;
        *(float4*)&Qs[row][c] = qv4;
    }
    __syncthreads();

    float4 qv[16];
#pragma unroll
    for (int d4 = 0; d4 < 16; d4++) qv[d4] = *(const float4*)&Qs[qi][d4 * 4];

    float Oacc[8] = {};
    float mrun = -INFINITY, lrun = 0.f;

    int rA0, rA1, rB0, rB1;
    if (qb < 64) { rA0 = q0;    rA1 = q0 + 16;                rB0 = N_TOK; rB1 = N_TOK + qb * 16; }
    else         { rA0 = N_TOK; rA1 = N_TOK + (qb - 63) * 16; rB0 = 0;     rB1 = 0; }

#pragma unroll 1
    for (int rng = 0; rng < 2; rng++) {
        int r0 = (rng == 0) ? rA0 : rB0;
        int r1 = (rng == 0) ? rA1 : rB1;
#pragma unroll 1
        for (int k0 = r0; k0 < r1; k0 += 64) {
            int nv = min(64, r1 - k0);
            __syncthreads();
#pragma unroll
            for (int i = 0; i < 8; i++) {
                int id = t + i * 128;
                int row = id >> 4, c = (id & 15) * 4;
                int src = min(k0 + row, S_TOK - 1);
                *(float4*)&Ks[row][c] = *(const float4*)&Kh[(size_t)src * HD + c];
                *(float4*)&Vs[row][c] = *(const float4*)&Vh[(size_t)src * HD + c];
            }
            __syncthreads();

            float s[8];
#pragma unroll
            for (int u = 0; u < 8; u++) s[u] = 0.f;
#pragma unroll
            for (int d4 = 0; d4 < 16; d4++) {
                float4 q = qv[d4];
#pragma unroll
                for (int u = 0; u < 8; u++) {
                    float4 kf = *(const float4*)&Ks[r8 + 8 * u][d4 * 4];
                    s[u] += q.x * kf.x + q.y * kf.y + q.z * kf.z + q.w * kf.w;
                }
            }
#pragma unroll
            for (int u = 0; u < 8; u++)
                if (r8 + 8 * u >= nv) s[u] = -INFINITY;

            float tmax = s[0];
#pragma unroll
            for (int u = 1; u < 8; u++) tmax = fmaxf(tmax, s[u]);
            tmax = fmaxf(tmax, __shfl_xor_sync(0xffffffffu, tmax, 1));
            tmax = fmaxf(tmax, __shfl_xor_sync(0xffffffffu, tmax, 2));
            tmax = fmaxf(tmax, __shfl_xor_sync(0xffffffffu, tmax, 4));

            float newm = fmaxf(mrun, tmax);
            float corr = __expf(mrun - newm);
            float tsum = 0.f;
#pragma unroll
            for (int u = 0; u < 8; u++) {
                float p = __expf(s[u] - newm);
                s[u] = p;
                tsum += p;
            }
            tsum += __shfl_xor_sync(0xffffffffu, tsum, 1);
            tsum += __shfl_xor_sync(0xffffffffu, tsum, 2);
            tsum += __shfl_xor_sync(0xffffffffu, tsum, 4);
            lrun = lrun * corr + tsum;
            mrun = newm;

#pragma unroll
            for (int u = 0; u < 8; u++) Ps[qi][r8 + 8 * u] = s[u];
#pragma unroll
            for (int i = 0; i < 8; i++) Oacc[i] *= corr;
            __syncthreads();

#pragma unroll 4
            for (int j = 0; j < 64; j++) {
                float p = Ps[qi][j];
                float4 v0 = *(const float4*)&Vs[j][r8 * 8];
                float4 v1 = *(const float4*)&Vs[j][r8 * 8 + 4];
                Oacc[0] += p * v0.x; Oacc[1] += p * v0.y;
                Oacc[2] += p * v0.z; Oacc[3] += p * v0.w;
                Oacc[4] += p * v1.x; Oacc[5] += p * v1.y;
                Oacc[6] += p * v1.z; Oacc[7] += p * v1.w;
            }
        }
    }

    float invl = 1.f / lrun;
    int row = q0 + qi;
    __half2 hv[4];
#pragma unroll
    for (int i = 0; i < 4; i++)
        hv[i] = __floats2half2_rn(Oacc[2*i] * invl, Oacc[2*i+1] * invl);
    *(float4*)&O[(size_t)row * D_MODEL + h * HD + r8 * 8] = *(float4*)hv;
}

// ---------------------------------------------------------------------------
// kernel_launch
// ---------------------------------------------------------------------------
extern "C" void kernel_launch(void* const* d_in, const int* in_sizes, int n_in,
                              void* d_out, int out_size) {
    const float* x          = (const float*)d_in[0];
    const float* c          = (const float*)d_in[1];
    const float* cosT       = (const float*)d_in[2];
    const float* sinT       = (const float*)d_in[3];
    const float* norm1_w    = (const float*)d_in[4];
    const float* qkv_w      = (const float*)d_in[5];
    const float* attn_out_w = (const float*)d_in[6];
    const float* norm2_w    = (const float*)d_in[7];
    const float* mlp_w1     = (const float*)d_in[8];
    const float* mlp_b1     = (const float*)d_in[9];
    const float* mlp_w2     = (const float*)d_in[10];
    const float* mlp_b2     = (const float*)d_in[11];
    const float* adaLN_w    = (const float*)d_in[12];
    const float* adaLN_b    = (const float*)d_in[13];
    float* out = (float*)d_out;

    float *mods, *Qp, *Kp, *Vp, *x2;
    __half *h, *h2, *Oh, *m1, *wq, *wo, *w1, *w2;
    cudaGetSymbolAddress((void**)&mods, g_mods);
    cudaGetSymbolAddress((void**)&h,    g_h);
    cudaGetSymbolAddress((void**)&h2,   g_h2);
    cudaGetSymbolAddress((void**)&Oh,   g_Oh);
    cudaGetSymbolAddress((void**)&m1,   g_m1);
    cudaGetSymbolAddress((void**)&Qp,   g_Q);
    cudaGetSymbolAddress((void**)&Kp,   g_K);
    cudaGetSymbolAddress((void**)&Vp,   g_V);
    cudaGetSymbolAddress((void**)&x2,   g_x2);
    cudaGetSymbolAddress((void**)&wq,   g_wq);
    cudaGetSymbolAddress((void**)&wo,   g_wo);
    cudaGetSymbolAddress((void**)&w1,   g_w1);
    cudaGetSymbolAddress((void**)&w2,   g_w2);

    const float* sh_msa = mods + 0 * D_MODEL;
    const float* sc_msa = mods + 1 * D_MODEL;
    const float* g_msa  = mods + 2 * D_MODEL;
    const float* sh_mlp = mods + 3 * D_MODEL;
    const float* sc_mlp = mods + 4 * D_MODEL;
    const float* g_mlp  = mods + 5 * D_MODEL;

    // weight conversion (once per launch)
    int n4q = 3 * D_MODEL * D_MODEL / 4;
    int n4o = D_MODEL * D_MODEL / 4;
    int n4m = D_MLP * D_MODEL / 4;
    f2h_kernel<<<(n4q + 255) / 256, 256>>>(qkv_w,      wq, n4q);
    f2h_kernel<<<(n4o + 255) / 256, 256>>>(attn_out_w, wo, n4o);
    f2h_kernel<<<(n4m + 255) / 256, 256>>>(mlp_w1,     w1, n4m);
    f2h_kernel<<<(n4m + 255) / 256, 256>>>(mlp_w2,     w2, n4m);

    adaln_kernel<<<(6 * D_MODEL + 127) / 128, 128>>>(c, adaLN_w, adaLN_b);

    ln_mod_kernel<<<S_TOK, 256>>>(x, norm1_w, sc_msa, sh_msa, h);

    // QKV GEMM + fused RoPE + head-major transpose
    gemm16<0><<<dim3(3 * D_MODEL / 128, S_TOK / 128), 128>>>(
        h, wq, nullptr, S_TOK, 3 * D_MODEL, D_MODEL,
        nullptr, nullptr, nullptr, cosT, sinT, Qp, Kp, Vp);

    attn_kernel<<<dim3(S_TOK / 16, H_HEADS), 128>>>(Oh);

    gemm16<1><<<dim3(D_MODEL / 128, S_TOK / 128), 128>>>(
        Oh, wo, x2, S_TOK, D_MODEL, D_MODEL,
        nullptr, g_msa, x, nullptr, nullptr, nullptr, nullptr, nullptr);

    ln_mod_kernel<<<S_TOK, 256>>>(x2, norm2_w, sc_mlp, sh_mlp, h2);

    gemm16<2><<<dim3(D_MLP / 128, S_TOK / 128), 128>>>(
        h2, w1, m1, S_TOK, D_MLP, D_MODEL,
        mlp_b1, nullptr, nullptr, nullptr, nullptr, nullptr, nullptr, nullptr);

    gemm16<3><<<dim3(D_MODEL / 128, S_TOK / 128), 128>>>(
        m1, w2, out, S_TOK, D_MODEL, D_MLP,
        mlp_b2, g_mlp, x2, nullptr, nullptr, nullptr, nullptr, nullptr);
}

// round 7
// speedup vs baseline: 8.2463x; 2.1567x over previous
#include <cuda_runtime.h>
#include <cuda_bf16.h>
#include <cuda_fp16.h>
#include <math.h>

// ---------------------------------------------------------------------------
// Problem constants
// ---------------------------------------------------------------------------
#define S_TOK   2048
#define N_TOK   1024
#define D_MODEL 1024
#define H_HEADS 16
#define HD      64
#define D_MLP   4096
#define COND    128
#define BSZ     16

// ---------------------------------------------------------------------------
// Device scratch
// ---------------------------------------------------------------------------
__device__ float  g_mods[6 * D_MODEL];
__device__ __half g_h  [S_TOK * D_MODEL];
__device__ __half g_h2 [S_TOK * D_MODEL];
__device__ __half g_Oh [S_TOK * D_MODEL];
__device__ __half g_m1 [S_TOK * D_MLP];
__device__ __half g_Qh [H_HEADS * S_TOK * HD];   // fp16, pre-scaled by 0.125
__device__ __half g_Kh [H_HEADS * S_TOK * HD];
__device__ __half g_Vt [H_HEADS * HD * S_TOK];   // TRANSPOSED: [head][dim][seq]
__device__ float  g_x2 [S_TOK * D_MODEL];
// fp16 weights (converted once per launch)
__device__ __half g_wq [3 * D_MODEL * D_MODEL];
__device__ __half g_wo [D_MODEL * D_MODEL];
__device__ __half g_w1 [D_MLP * D_MODEL];
__device__ __half g_w2 [D_MODEL * D_MLP];

// ---------------------------------------------------------------------------
// fp32 -> fp16 convert (vectorized)
// ---------------------------------------------------------------------------
__global__ void f2h_kernel(const float* __restrict__ src, __half* __restrict__ dst, int n4) {
    int i = blockIdx.x * blockDim.x + threadIdx.x;
    if (i >= n4) return;
    float4 v = ((const float4*)src)[i];
    __half2 h0 = __floats2half2_rn(v.x, v.y);
    __half2 h1 = __floats2half2_rn(v.z, v.w);
    ((__half2*)dst)[2 * i]     = h0;
    ((__half2*)dst)[2 * i + 1] = h1;
}

// ---------------------------------------------------------------------------
// adaLN
// ---------------------------------------------------------------------------
__global__ void adaln_kernel(const float* __restrict__ c,
                             const float* __restrict__ W,
                             const float* __restrict__ b) {
    __shared__ float cs[COND];
    int tid = threadIdx.x;
    if (tid < COND) cs[tid] = c[tid];
    __syncthreads();
    int i = blockIdx.x * blockDim.x + tid;
    if (i >= 6 * D_MODEL) return;
    const float* w = W + (size_t)i * COND;
    float acc = 0.f;
#pragma unroll 8
    for (int j = 0; j < COND; j++) acc += w[j] * cs[j];
    g_mods[i] = acc + b[i];
}

// ---------------------------------------------------------------------------
// LayerNorm + modulate -> fp16 output
// ---------------------------------------------------------------------------
__inline__ __device__ float warp_reduce_sum(float v) {
#pragma unroll
    for (int o = 16; o > 0; o >>= 1) v += __shfl_xor_sync(0xffffffffu, v, o);
    return v;
}

__global__ void ln_mod_kernel(const float* __restrict__ X,
                              const float* __restrict__ w,
                              const float* __restrict__ sc,
                              const float* __restrict__ sh,
                              __half* __restrict__ out) {
    int row = blockIdx.x;
    const float4* x4 = (const float4*)(X + (size_t)row * D_MODEL);
    int tid = threadIdx.x;
    float4 v = x4[tid];
    float s  = v.x + v.y + v.z + v.w;
    float ss = v.x*v.x + v.y*v.y + v.z*v.z + v.w*v.w;
    __shared__ float red_s[8], red_ss[8];
    s  = warp_reduce_sum(s);
    ss = warp_reduce_sum(ss);
    int wid = tid >> 5, lid = tid & 31;
    if (lid == 0) { red_s[wid] = s; red_ss[wid] = ss; }
    __syncthreads();
    if (wid == 0) {
        float a = (lid < 8) ? red_s[lid]  : 0.f;
        float b = (lid < 8) ? red_ss[lid] : 0.f;
        a = warp_reduce_sum(a);
        b = warp_reduce_sum(b);
        if (lid == 0) { red_s[0] = a; red_ss[0] = b; }
    }
    __syncthreads();
    float mu  = red_s[0] * (1.f / D_MODEL);
    float var = red_ss[0] * (1.f / D_MODEL) - mu * mu;
    float inv = rsqrtf(var + 1e-5f);
    int d0 = tid * 4;
    float vv[4] = {v.x, v.y, v.z, v.w};
    float o[4];
#pragma unroll
    for (int i = 0; i < 4; i++) {
        int d = d0 + i;
        o[i] = (vv[i] - mu) * inv * w[d] * (1.f + sc[d]) + sh[d];
    }
    __half2 h0 = __floats2half2_rn(o[0], o[1]);
    __half2 h1 = __floats2half2_rn(o[2], o[3]);
    *(__half2*)&out[(size_t)row * D_MODEL + d0]     = h0;
    *(__half2*)&out[(size_t)row * D_MODEL + d0 + 2] = h1;
}

// ---------------------------------------------------------------------------
// Common PTX helpers
// ---------------------------------------------------------------------------
__device__ __forceinline__ float gelu_tanh(float x) {
    float x3 = x * x * x;
    return 0.5f * x * (1.f + tanhf(0.7978845608028654f * (x + 0.044715f * x3)));
}

__device__ __forceinline__ void cp16(void* dst, const void* src) {
    unsigned d = (unsigned)__cvta_generic_to_shared(dst);
    asm volatile("cp.async.cg.shared.global [%0], [%1], 16;\n" :: "r"(d), "l"(src));
}

__device__ __forceinline__ void ldsm4(unsigned& r0, unsigned& r1, unsigned& r2, unsigned& r3,
                                      const __half* p) {
    unsigned a = (unsigned)__cvta_generic_to_shared(p);
    asm volatile("ldmatrix.sync.aligned.m8n8.x4.shared.b16 {%0,%1,%2,%3}, [%4];\n"
                 : "=r"(r0), "=r"(r1), "=r"(r2), "=r"(r3) : "r"(a));
}

__device__ __forceinline__ void mma_fp16(float* c, const unsigned* a, const unsigned* b) {
    asm volatile(
        "mma.sync.aligned.m16n8k16.row.col.f32.f16.f16.f32 "
        "{%0,%1,%2,%3}, {%4,%5,%6,%7}, {%8,%9}, {%0,%1,%2,%3};\n"
        : "+f"(c[0]), "+f"(c[1]), "+f"(c[2]), "+f"(c[3])
        : "r"(a[0]), "r"(a[1]), "r"(a[2]), "r"(a[3]), "r"(b[0]), "r"(b[1]));
}

__device__ __forceinline__ unsigned packp(float x, float y) {
    __half2 h = __floats2half2_rn(x, y);
    return *(unsigned*)&h;
}

// ---------------------------------------------------------------------------
// FP16 GEMM with cp.async + ldmatrix (unchanged core from R6).
// EPI: 0 qkv+rope -> Qh/Kh fp16 + Vt fp16 transposed, 1 gate*acc+res -> fp32,
//      2 gelu(acc+bias) -> fp16, 3 gate*(acc+bias)+res -> fp32
// ---------------------------------------------------------------------------
template<int EPI>
__global__ void __launch_bounds__(128, 2)
gemm16(const __half* __restrict__ A, const __half* __restrict__ B,
       void* __restrict__ Cout, int M, int N, int K,
       const float* __restrict__ bias, const float* __restrict__ gate,
       const float* __restrict__ res,
       const float* __restrict__ cosT, const float* __restrict__ sinT,
       __half* __restrict__ Qp, __half* __restrict__ Kp, __half* __restrict__ Vtp) {
    __shared__ __half As[2][128 * 32];
    __shared__ __half Bs[2][128 * 32];

    const int m0 = blockIdx.y * 128;
    const int n0 = blockIdx.x * 128;
    const int tid  = threadIdx.x;
    const int lane = tid & 31;
    const int warp = tid >> 5;
    const int wm = (warp >> 1) * 64;
    const int wn = (warp & 1) * 64;
    const int g  = lane >> 2;
    const int tg = lane & 3;
    const int sr  = tid >> 2;
    const int scn = tid & 3;

    float acc[4][8][4] = {};
    const int nT = K / 32;

    const int lrow = lane & 7;
    const int a_r8 = ((lane >> 3) & 1) * 8;
    const int a_cb = (lane >> 4) & 1;
    const int b_r8 = ((lane >> 4) & 1) * 8;
    const int b_cb = (lane >> 3) & 1;

    auto issue = [&](int b, int k0) {
#pragma unroll
        for (int i = 0; i < 4; i++) {
            int r  = sr + 32 * i;
            int sw = scn ^ ((r >> 1) & 3);
            cp16(&As[b][r * 32 + sw * 8], &A[(size_t)(m0 + r) * K + k0 + scn * 8]);
            cp16(&Bs[b][r * 32 + sw * 8], &B[(size_t)(n0 + r) * K + k0 + scn * 8]);
        }
        asm volatile("cp.async.commit_group;\n");
    };

    issue(0, 0);

    for (int t = 0; t < nT; t++) {
        asm volatile("cp.async.wait_group 0;\n");
        __syncthreads();
        if (t + 1 < nT) issue((t + 1) & 1, (t + 1) * 32);

        const __half* sA = As[t & 1];
        const __half* sB = Bs[t & 1];
#pragma unroll
        for (int kk = 0; kk < 2; kk++) {
            unsigned af[4][4], bf[8][2];
#pragma unroll
            for (int i = 0; i < 4; i++) {
                int mr = wm + i * 16 + lrow + a_r8;
                int ch = 2 * kk + a_cb;
                int sw = ch ^ ((mr >> 1) & 3);
                ldsm4(af[i][0], af[i][1], af[i][2], af[i][3], &sA[mr * 32 + sw * 8]);
            }
#pragma unroll
            for (int jp = 0; jp < 4; jp++) {
                int nr = wn + jp * 16 + lrow + b_r8;
                int ch = 2 * kk + b_cb;
                int sw = ch ^ ((nr >> 1) & 3);
                ldsm4(bf[2*jp][0], bf[2*jp][1], bf[2*jp+1][0], bf[2*jp+1][1],
                      &sB[nr * 32 + sw * 8]);
            }
#pragma unroll
            for (int i = 0; i < 4; i++)
#pragma unroll
                for (int j = 0; j < 8; j++)
                    mma_fp16(acc[i][j], af[i], bf[j]);
        }
        __syncthreads();
    }

    // ---------------- epilogues ----------------
    if (EPI == 0) {
        // qkv + rope: warp's 64-col block = one (q/k/v, head)
        int colBlock = n0 + wn;
        int qidx = colBlock >> 10;
        int head = (colBlock & 1023) >> 6;
#pragma unroll
        for (int i = 0; i < 4; i++) {
#pragma unroll
            for (int hh = 0; hh < 2; hh++) {
                int row = m0 + wm + i * 16 + g + hh * 8;
                int p = row & (N_TOK - 1);
#pragma unroll
                for (int j = 0; j < 4; j++) {
                    float o1[2], o2[2];
#pragma unroll
                    for (int cc = 0; cc < 2; cc++) {
                        int d = j * 8 + tg * 2 + cc;
                        float x1 = acc[i][j][hh * 2 + cc];
                        float x2 = acc[i][j + 4][hh * 2 + cc];
                        float cs = cosT[p * 32 + d];
                        float sn = sinT[p * 32 + d];
                        o1[cc] = x1 * cs - x2 * sn;
                        o2[cc] = x2 * cs + x1 * sn;
                    }
                    int d0 = j * 8 + tg * 2;
                    if (qidx == 0) {
                        __half* dst = Qp + ((size_t)head * S_TOK + row) * HD;
                        *(__half2*)&dst[d0]      = __floats2half2_rn(o1[0]*0.125f, o1[1]*0.125f);
                        *(__half2*)&dst[d0 + 32] = __floats2half2_rn(o2[0]*0.125f, o2[1]*0.125f);
                    } else if (qidx == 1) {
                        __half* dst = Kp + ((size_t)head * S_TOK + row) * HD;
                        *(__half2*)&dst[d0]      = __floats2half2_rn(o1[0], o1[1]);
                        *(__half2*)&dst[d0 + 32] = __floats2half2_rn(o2[0], o2[1]);
                    } else {
                        // transposed: Vt[head][dim][seq]
                        __half* dst = Vtp + (size_t)head * HD * S_TOK;
                        dst[(size_t)(d0)      * S_TOK + row] = __float2half(o1[0]);
                        dst[(size_t)(d0 + 1)  * S_TOK + row] = __float2half(o1[1]);
                        dst[(size_t)(d0 + 32) * S_TOK + row] = __float2half(o2[0]);
                        dst[(size_t)(d0 + 33) * S_TOK + row] = __float2half(o2[1]);
                    }
                }
            }
        }
        return;
    }

#pragma unroll
    for (int i = 0; i < 4; i++) {
        int row0 = m0 + wm + i * 16 + g;
#pragma unroll
        for (int j = 0; j < 8; j++) {
            int col = n0 + wn + j * 8 + tg * 2;
#pragma unroll
            for (int hh = 0; hh < 2; hh++) {
                int row = row0 + hh * 8;
                float v0 = acc[i][j][hh * 2 + 0];
                float v1 = acc[i][j][hh * 2 + 1];
                if (EPI == 1) {
                    float* C = (float*)Cout;
                    C[(size_t)row * N + col]     = gate[col] * v0 + res[(size_t)row * N + col];
                    C[(size_t)row * N + col + 1] = gate[col+1] * v1 + res[(size_t)row * N + col + 1];
                } else if (EPI == 2) {
                    __half* C = (__half*)Cout;
                    __half2 hv = __floats2half2_rn(gelu_tanh(v0 + bias[col]),
                                                   gelu_tanh(v1 + bias[col + 1]));
                    *(__half2*)&C[(size_t)row * N + col] = hv;
                } else {
                    float* C = (float*)Cout;
                    C[(size_t)row * N + col]     = gate[col] * (v0 + bias[col]) + res[(size_t)row * N + col];
                    C[(size_t)row * N + col + 1] = gate[col+1] * (v1 + bias[col+1]) + res[(size_t)row * N + col + 1];
                }
            }
        }
    }
}

// ---------------------------------------------------------------------------
// FP16 MMA block-diffusion attention (FlashAttention-2 style).
// CTA = (16-query block qb, head h), 4 warps, 64-key tiles.
//   qb < 64 (noisy):  keys [qb*16, qb*16+16)  U  [1024, 1024 + qb*16)
//   qb >= 64 (clean): keys [1024, 1024 + (qb-63)*16)
// Each warp: full 16x64 score tile (32 mma), register online softmax,
// P c-frags repacked as A-frags, PV over its own 16 output dims (8 mma).
// Smem rows 64 halves (128B), swizzle chunk' = chunk ^ (row & 7).
// ---------------------------------------------------------------------------
__global__ void __launch_bounds__(128)
attn_kernel(__half* __restrict__ O) {
    __shared__ __half Qs[16 * 64];
    __shared__ __half Ks[2][64 * 64];
    __shared__ __half Vs[2][64 * 64];   // Vt tile: [dim][key]

    const int qb = blockIdx.x;
    const int h  = blockIdx.y;
    const int t  = threadIdx.x;
    const int lane = t & 31;
    const int warp = t >> 5;
    const int g  = lane >> 2;
    const int tg = lane & 3;
    const int lrow = lane & 7;
    const int a_r8 = ((lane >> 3) & 1) * 8;
    const int a_cb = (lane >> 4) & 1;
    const int b_r8 = ((lane >> 4) & 1) * 8;
    const int b_cb = (lane >> 3) & 1;

    const int q0 = qb * 16;
    const __half* Qg = g_Qh + ((size_t)h * S_TOK + q0) * HD;
    const __half* Kg = g_Kh + (size_t)h * S_TOK * HD;
    const __half* Vg = g_Vt + (size_t)h * HD * S_TOK;

    // tile schedule
    const int t1n  = (qb < 64) ? 1 : 0;                       // 16-key diag tile
    const int lenB = (qb < 64) ? qb * 16 : (qb - 63) * 16;    // clean prefix length
    const int nT   = t1n + ((lenB + 63) >> 6);

    auto tile_k0 = [&](int ti) {
        return (t1n && ti == 0) ? q0 : N_TOK + (ti - t1n) * 64;
    };
    auto tile_nv = [&](int ti) {
        return (t1n && ti == 0) ? 16 : min(64, lenB - (ti - t1n) * 64);
    };

    // Q: 16 rows x 8 chunks = 128 cp.async, one per thread
    {
        int row = t >> 3, ch = t & 7;
        cp16(&Qs[row * 64 + (ch ^ (row & 7)) * 8], &Qg[row * 64 + ch * 8]);
    }
    auto issueKV = [&](int b, int k0) {
#pragma unroll
        for (int i = 0; i < 4; i++) {
            int idx = t + i * 128;          // 512 chunks
            int row = idx >> 3, ch = idx & 7;
            int sw  = (ch ^ (row & 7)) * 8;
            int src = min(k0 + row, S_TOK - 1);
            cp16(&Ks[b][row * 64 + sw], &Kg[(size_t)src * HD + ch * 8]);
            cp16(&Vs[b][row * 64 + sw], &Vg[(size_t)row * S_TOK + k0 + ch * 8]);
        }
        asm volatile("cp.async.commit_group;\n");
    };
    issueKV(0, tile_k0(0));

    unsigned aq[4][4];                 // Q A-frags (loaded once)
    float Oacc[2][4] = {};
    float m0run = -INFINITY, m1run = -INFINITY;
    float l0run = 0.f, l1run = 0.f;

    for (int ti = 0; ti < nT; ti++) {
        asm volatile("cp.async.wait_group 0;\n");
        __syncthreads();
        if (ti == 0) {
#pragma unroll
            for (int kb = 0; kb < 4; kb++) {
                int r  = lrow + a_r8;
                int ch = 2 * kb + a_cb;
                ldsm4(aq[kb][0], aq[kb][1], aq[kb][2], aq[kb][3],
                      &Qs[r * 64 + (ch ^ (r & 7)) * 8]);
            }
        }
        if (ti + 1 < nT) issueKV((ti + 1) & 1, tile_k0(ti + 1));

        const __half* sK = Ks[ti & 1];
        const __half* sV = Vs[ti & 1];
        const int nv = tile_nv(ti);

        // ---- scores: 16x64, all keys, this warp ----
        float sc[8][4] = {};
#pragma unroll
        for (int kb = 0; kb < 4; kb++) {
            unsigned bf[8][2];
#pragma unroll
            for (int pr = 0; pr < 4; pr++) {
                int r  = pr * 16 + lrow + b_r8;
                int ch = 2 * kb + b_cb;
                ldsm4(bf[2*pr][0], bf[2*pr][1], bf[2*pr+1][0], bf[2*pr+1][1],
                      &sK[r * 64 + (ch ^ (r & 7)) * 8]);
            }
#pragma unroll
            for (int nb = 0; nb < 8; nb++)
                mma_fp16(sc[nb], aq[kb], bf[nb]);
        }
        // mask whole 8-key blocks (nv is a multiple of 16)
#pragma unroll
        for (int nb = 0; nb < 8; nb++)
            if (nb * 8 >= nv) { sc[nb][0] = sc[nb][1] = sc[nb][2] = sc[nb][3] = -INFINITY; }

        // ---- online softmax (rows g and g+8) ----
        float mx0 = -INFINITY, mx1 = -INFINITY;
#pragma unroll
        for (int nb = 0; nb < 8; nb++) {
            mx0 = fmaxf(mx0, fmaxf(sc[nb][0], sc[nb][1]));
            mx1 = fmaxf(mx1, fmaxf(sc[nb][2], sc[nb][3]));
        }
        mx0 = fmaxf(mx0, __shfl_xor_sync(0xffffffffu, mx0, 1));
        mx0 = fmaxf(mx0, __shfl_xor_sync(0xffffffffu, mx0, 2));
        mx1 = fmaxf(mx1, __shfl_xor_sync(0xffffffffu, mx1, 1));
        mx1 = fmaxf(mx1, __shfl_xor_sync(0xffffffffu, mx1, 2));

        float nm0 = fmaxf(m0run, mx0), nm1 = fmaxf(m1run, mx1);
        float c0 = __expf(m0run - nm0), c1 = __expf(m1run - nm1);
        float ts0 = 0.f, ts1 = 0.f;
#pragma unroll
        for (int nb = 0; nb < 8; nb++) {
            sc[nb][0] = __expf(sc[nb][0] - nm0);
            sc[nb][1] = __expf(sc[nb][1] - nm0);
            sc[nb][2] = __expf(sc[nb][2] - nm1);
            sc[nb][3] = __expf(sc[nb][3] - nm1);
            ts0 += sc[nb][0] + sc[nb][1];
            ts1 += sc[nb][2] + sc[nb][3];
        }
        ts0 += __shfl_xor_sync(0xffffffffu, ts0, 1);
        ts0 += __shfl_xor_sync(0xffffffffu, ts0, 2);
        ts1 += __shfl_xor_sync(0xffffffffu, ts1, 1);
        ts1 += __shfl_xor_sync(0xffffffffu, ts1, 2);
        l0run = l0run * c0 + ts0;  m0run = nm0;
        l1run = l1run * c1 + ts1;  m1run = nm1;

        Oacc[0][0] *= c0; Oacc[0][1] *= c0; Oacc[0][2] *= c1; Oacc[0][3] *= c1;
        Oacc[1][0] *= c0; Oacc[1][1] *= c0; Oacc[1][2] *= c1; Oacc[1][3] *= c1;

        // ---- repack P c-frags as A-frags ----
        unsigned ap[4][4];
#pragma unroll
        for (int kb2 = 0; kb2 < 4; kb2++) {
            ap[kb2][0] = packp(sc[2*kb2][0],   sc[2*kb2][1]);
            ap[kb2][1] = packp(sc[2*kb2][2],   sc[2*kb2][3]);
            ap[kb2][2] = packp(sc[2*kb2+1][0], sc[2*kb2+1][1]);
            ap[kb2][3] = packp(sc[2*kb2+1][2], sc[2*kb2+1][3]);
        }

        // ---- PV: this warp's 16 output dims ----
#pragma unroll
        for (int kb2 = 0; kb2 < 4; kb2++) {
            unsigned bv0[2], bv1[2];
            int r  = warp * 16 + lrow + b_r8;         // Vt dim rows
            int ch = 2 * kb2 + b_cb;                  // key chunk
            ldsm4(bv0[0], bv0[1], bv1[0], bv1[1],
                  &sV[r * 64 + (ch ^ (r & 7)) * 8]);
            mma_fp16(Oacc[0], ap[kb2], bv0);
            mma_fp16(Oacc[1], ap[kb2], bv1);
        }
        __syncthreads();
    }

    // ---- epilogue ----
    float inv0 = 1.f / l0run, inv1 = 1.f / l1run;
    int row0 = q0 + g, row1 = q0 + g + 8;
#pragma unroll
    for (int nb2 = 0; nb2 < 2; nb2++) {
        int col = h * HD + warp * 16 + nb2 * 8 + tg * 2;
        *(__half2*)&O[(size_t)row0 * D_MODEL + col] =
            __floats2half2_rn(Oacc[nb2][0] * inv0, Oacc[nb2][1] * inv0);
        *(__half2*)&O[(size_t)row1 * D_MODEL + col] =
            __floats2half2_rn(Oacc[nb2][2] * inv1, Oacc[nb2][3] * inv1);
    }
}

// ---------------------------------------------------------------------------
// kernel_launch
// ---------------------------------------------------------------------------
extern "C" void kernel_launch(void* const* d_in, const int* in_sizes, int n_in,
                              void* d_out, int out_size) {
    const float* x          = (const float*)d_in[0];
    const float* c          = (const float*)d_in[1];
    const float* cosT       = (const float*)d_in[2];
    const float* sinT       = (const float*)d_in[3];
    const float* norm1_w    = (const float*)d_in[4];
    const float* qkv_w      = (const float*)d_in[5];
    const float* attn_out_w = (const float*)d_in[6];
    const float* norm2_w    = (const float*)d_in[7];
    const float* mlp_w1     = (const float*)d_in[8];
    const float* mlp_b1     = (const float*)d_in[9];
    const float* mlp_w2     = (const float*)d_in[10];
    const float* mlp_b2     = (const float*)d_in[11];
    const float* adaLN_w    = (const float*)d_in[12];
    const float* adaLN_b    = (const float*)d_in[13];
    float* out = (float*)d_out;

    float *mods, *x2;
    __half *h, *h2, *Oh, *m1, *Qp, *Kp, *Vtp, *wq, *wo, *w1, *w2;
    cudaGetSymbolAddress((void**)&mods, g_mods);
    cudaGetSymbolAddress((void**)&h,    g_h);
    cudaGetSymbolAddress((void**)&h2,   g_h2);
    cudaGetSymbolAddress((void**)&Oh,   g_Oh);
    cudaGetSymbolAddress((void**)&m1,   g_m1);
    cudaGetSymbolAddress((void**)&Qp,   g_Qh);
    cudaGetSymbolAddress((void**)&Kp,   g_Kh);
    cudaGetSymbolAddress((void**)&Vtp,  g_Vt);
    cudaGetSymbolAddress((void**)&x2,   g_x2);
    cudaGetSymbolAddress((void**)&wq,   g_wq);
    cudaGetSymbolAddress((void**)&wo,   g_wo);
    cudaGetSymbolAddress((void**)&w1,   g_w1);
    cudaGetSymbolAddress((void**)&w2,   g_w2);

    const float* sh_msa = mods + 0 * D_MODEL;
    const float* sc_msa = mods + 1 * D_MODEL;
    const float* g_msa  = mods + 2 * D_MODEL;
    const float* sh_mlp = mods + 3 * D_MODEL;
    const float* sc_mlp = mods + 4 * D_MODEL;
    const float* g_mlp  = mods + 5 * D_MODEL;

    int n4q = 3 * D_MODEL * D_MODEL / 4;
    int n4o = D_MODEL * D_MODEL / 4;
    int n4m = D_MLP * D_MODEL / 4;
    f2h_kernel<<<(n4q + 255) / 256, 256>>>(qkv_w,      wq, n4q);
    f2h_kernel<<<(n4o + 255) / 256, 256>>>(attn_out_w, wo, n4o);
    f2h_kernel<<<(n4m + 255) / 256, 256>>>(mlp_w1,     w1, n4m);
    f2h_kernel<<<(n4m + 255) / 256, 256>>>(mlp_w2,     w2, n4m);

    adaln_kernel<<<(6 * D_MODEL + 127) / 128, 128>>>(c, adaLN_w, adaLN_b);

    ln_mod_kernel<<<S_TOK, 256>>>(x, norm1_w, sc_msa, sh_msa, h);

    gemm16<0><<<dim3(3 * D_MODEL / 128, S_TOK / 128), 128>>>(
        h, wq, nullptr, S_TOK, 3 * D_MODEL, D_MODEL,
        nullptr, nullptr, nullptr, cosT, sinT, Qp, Kp, Vtp);

    attn_kernel<<<dim3(S_TOK / 16, H_HEADS), 128>>>(Oh);

    gemm16<1><<<dim3(D_MODEL / 128, S_TOK / 128), 128>>>(
        Oh, wo, x2, S_TOK, D_MODEL, D_MODEL,
        nullptr, g_msa, x, nullptr, nullptr, nullptr, nullptr, nullptr);

    ln_mod_kernel<<<S_TOK, 256>>>(x2, norm2_w, sc_mlp, sh_mlp, h2);

    gemm16<2><<<dim3(D_MLP / 128, S_TOK / 128), 128>>>(
        h2, w1, m1, S_TOK, D_MLP, D_MODEL,
        mlp_b1, nullptr, nullptr, nullptr, nullptr, nullptr, nullptr, nullptr);

    gemm16<3><<<dim3(D_MODEL / 128, S_TOK / 128), 128>>>(
        m1, w2, out, S_TOK, D_MODEL, D_MLP,
        mlp_b2, g_mlp, x2, nullptr, nullptr, nullptr, nullptr, nullptr);
}

// round 8
// speedup vs baseline: 9.0626x; 1.0990x over previous
#include <cuda_runtime.h>
#include <cuda_bf16.h>
#include <cuda_fp16.h>
#include <math.h>

// ---------------------------------------------------------------------------
// Problem constants
// ---------------------------------------------------------------------------
#define S_TOK   2048
#define N_TOK   1024
#define D_MODEL 1024
#define H_HEADS 16
#define HD      64
#define D_MLP   4096
#define COND    128
#define BSZ     16

// ---------------------------------------------------------------------------
// Device scratch
// ---------------------------------------------------------------------------
__device__ float  g_mods[6 * D_MODEL];
__device__ __half g_h  [S_TOK * D_MODEL];
__device__ __half g_h2 [S_TOK * D_MODEL];
__device__ __half g_Oh [S_TOK * D_MODEL];
__device__ __half g_m1 [S_TOK * D_MLP];
__device__ __half g_Qh [H_HEADS * S_TOK * HD];   // fp16, pre-scaled by 0.125
__device__ __half g_Kh [H_HEADS * S_TOK * HD];
__device__ __half g_Vt [H_HEADS * HD * S_TOK];   // TRANSPOSED: [head][dim][seq]
__device__ float  g_x2 [S_TOK * D_MODEL];
// fp16 weights (converted once per launch)
__device__ __half g_wq [3 * D_MODEL * D_MODEL];
__device__ __half g_wo [D_MODEL * D_MODEL];
__device__ __half g_w1 [D_MLP * D_MODEL];
__device__ __half g_w2 [D_MODEL * D_MLP];

// ---------------------------------------------------------------------------
// fp32 -> fp16 convert: all four weight arrays in ONE grid-stride kernel
// segment sizes in float4 units
// ---------------------------------------------------------------------------
#define N4Q (3 * D_MODEL * D_MODEL / 4)
#define N4O (D_MODEL * D_MODEL / 4)
#define N4M (D_MLP * D_MODEL / 4)
#define N4TOT (N4Q + N4O + N4M + N4M)

__global__ void f2h_all(const float* __restrict__ wq, const float* __restrict__ wo,
                        const float* __restrict__ w1, const float* __restrict__ w2) {
    int i = blockIdx.x * blockDim.x + threadIdx.x;
    if (i >= N4TOT) return;
    const float* src;
    __half* dst;
    int off;
    if (i < N4Q)                { src = wq; dst = g_wq; off = i; }
    else if (i < N4Q + N4O)     { src = wo; dst = g_wo; off = i - N4Q; }
    else if (i < N4Q + N4O + N4M) { src = w1; dst = g_w1; off = i - N4Q - N4O; }
    else                        { src = w2; dst = g_w2; off = i - N4Q - N4O - N4M; }
    float4 v = ((const float4*)src)[off];
    __half2 h0 = __floats2half2_rn(v.x, v.y);
    __half2 h1 = __floats2half2_rn(v.z, v.w);
    ((__half2*)dst)[2 * off]     = h0;
    ((__half2*)dst)[2 * off + 1] = h1;
}

// ---------------------------------------------------------------------------
// adaLN
// ---------------------------------------------------------------------------
__global__ void adaln_kernel(const float* __restrict__ c,
                             const float* __restrict__ W,
                             const float* __restrict__ b) {
    __shared__ float cs[COND];
    int tid = threadIdx.x;
    if (tid < COND) cs[tid] = c[tid];
    __syncthreads();
    int i = blockIdx.x * blockDim.x + tid;
    if (i >= 6 * D_MODEL) return;
    const float* w = W + (size_t)i * COND;
    float acc = 0.f;
#pragma unroll 8
    for (int j = 0; j < COND; j++) acc += w[j] * cs[j];
    g_mods[i] = acc + b[i];
}

// ---------------------------------------------------------------------------
// LayerNorm + modulate -> fp16 output
// ---------------------------------------------------------------------------
__inline__ __device__ float warp_reduce_sum(float v) {
#pragma unroll
    for (int o = 16; o > 0; o >>= 1) v += __shfl_xor_sync(0xffffffffu, v, o);
    return v;
}

__global__ void ln_mod_kernel(const float* __restrict__ X,
                              const float* __restrict__ w,
                              const float* __restrict__ sc,
                              const float* __restrict__ sh,
                              __half* __restrict__ out) {
    int row = blockIdx.x;
    const float4* x4 = (const float4*)(X + (size_t)row * D_MODEL);
    int tid = threadIdx.x;
    float4 v = x4[tid];
    float s  = v.x + v.y + v.z + v.w;
    float ss = v.x*v.x + v.y*v.y + v.z*v.z + v.w*v.w;
    __shared__ float red_s[8], red_ss[8];
    s  = warp_reduce_sum(s);
    ss = warp_reduce_sum(ss);
    int wid = tid >> 5, lid = tid & 31;
    if (lid == 0) { red_s[wid] = s; red_ss[wid] = ss; }
    __syncthreads();
    if (wid == 0) {
        float a = (lid < 8) ? red_s[lid]  : 0.f;
        float b = (lid < 8) ? red_ss[lid] : 0.f;
        a = warp_reduce_sum(a);
        b = warp_reduce_sum(b);
        if (lid == 0) { red_s[0] = a; red_ss[0] = b; }
    }
    __syncthreads();
    float mu  = red_s[0] * (1.f / D_MODEL);
    float var = red_ss[0] * (1.f / D_MODEL) - mu * mu;
    float inv = rsqrtf(var + 1e-5f);
    int d0 = tid * 4;
    float vv[4] = {v.x, v.y, v.z, v.w};
    float o[4];
#pragma unroll
    for (int i = 0; i < 4; i++) {
        int d = d0 + i;
        o[i] = (vv[i] - mu) * inv * w[d] * (1.f + sc[d]) + sh[d];
    }
    __half2 h0 = __floats2half2_rn(o[0], o[1]);
    __half2 h1 = __floats2half2_rn(o[2], o[3]);
    *(__half2*)&out[(size_t)row * D_MODEL + d0]     = h0;
    *(__half2*)&out[(size_t)row * D_MODEL + d0 + 2] = h1;
}

// ---------------------------------------------------------------------------
// Common PTX helpers
// ---------------------------------------------------------------------------
__device__ __forceinline__ float gelu_tanh(float x) {
    float x3 = x * x * x;
    return 0.5f * x * (1.f + tanhf(0.7978845608028654f * (x + 0.044715f * x3)));
}

__device__ __forceinline__ void cp16(void* dst, const void* src) {
    unsigned d = (unsigned)__cvta_generic_to_shared(dst);
    asm volatile("cp.async.cg.shared.global [%0], [%1], 16;\n" :: "r"(d), "l"(src));
}

__device__ __forceinline__ void ldsm4(unsigned& r0, unsigned& r1, unsigned& r2, unsigned& r3,
                                      const __half* p) {
    unsigned a = (unsigned)__cvta_generic_to_shared(p);
    asm volatile("ldmatrix.sync.aligned.m8n8.x4.shared.b16 {%0,%1,%2,%3}, [%4];\n"
                 : "=r"(r0), "=r"(r1), "=r"(r2), "=r"(r3) : "r"(a));
}

__device__ __forceinline__ void mma_fp16(float* c, const unsigned* a, const unsigned* b) {
    asm volatile(
        "mma.sync.aligned.m16n8k16.row.col.f32.f16.f16.f32 "
        "{%0,%1,%2,%3}, {%4,%5,%6,%7}, {%8,%9}, {%0,%1,%2,%3};\n"
        : "+f"(c[0]), "+f"(c[1]), "+f"(c[2]), "+f"(c[3])
        : "r"(a[0]), "r"(a[1]), "r"(a[2]), "r"(a[3]), "r"(b[0]), "r"(b[1]));
}

__device__ __forceinline__ unsigned packp(float x, float y) {
    __half2 h = __floats2half2_rn(x, y);
    return *(unsigned*)&h;
}

// ---------------------------------------------------------------------------
// FP16 GEMM, cp.async + ldmatrix, 3-stage pipeline, ONE barrier per k-tile.
// EPI: 0 qkv+rope -> Qh/Kh fp16 + Vt fp16 transposed, 1 gate*acc+res -> fp32,
//      2 gelu(acc+bias) -> fp16, 3 gate*(acc+bias)+res -> fp32
// ---------------------------------------------------------------------------
template<int EPI>
__global__ void __launch_bounds__(128, 2)
gemm16(const __half* __restrict__ A, const __half* __restrict__ B,
       void* __restrict__ Cout, int M, int N, int K,
       const float* __restrict__ bias, const float* __restrict__ gate,
       const float* __restrict__ res,
       const float* __restrict__ cosT, const float* __restrict__ sinT,
       __half* __restrict__ Qp, __half* __restrict__ Kp, __half* __restrict__ Vtp) {
    __shared__ __half As[3][128 * 32];
    __shared__ __half Bs[3][128 * 32];

    const int m0 = blockIdx.y * 128;
    const int n0 = blockIdx.x * 128;
    const int tid  = threadIdx.x;
    const int lane = tid & 31;
    const int warp = tid >> 5;
    const int wm = (warp >> 1) * 64;
    const int wn = (warp & 1) * 64;
    const int g  = lane >> 2;
    const int tg = lane & 3;
    const int sr  = tid >> 2;
    const int scn = tid & 3;

    float acc[4][8][4] = {};
    const int nT = K / 32;

    const int lrow = lane & 7;
    const int a_r8 = ((lane >> 3) & 1) * 8;
    const int a_cb = (lane >> 4) & 1;
    const int b_r8 = ((lane >> 4) & 1) * 8;
    const int b_cb = (lane >> 3) & 1;

    auto issue = [&](int b, int k0) {
#pragma unroll
        for (int i = 0; i < 4; i++) {
            int r  = sr + 32 * i;
            int sw = scn ^ ((r >> 1) & 3);
            cp16(&As[b][r * 32 + sw * 8], &A[(size_t)(m0 + r) * K + k0 + scn * 8]);
            cp16(&Bs[b][r * 32 + sw * 8], &B[(size_t)(n0 + r) * K + k0 + scn * 8]);
        }
        asm volatile("cp.async.commit_group;\n");
    };

    issue(0, 0);
    issue(1, 32);

    for (int t = 0; t < nT; t++) {
        if (t + 1 < nT) asm volatile("cp.async.wait_group 1;\n");
        else            asm volatile("cp.async.wait_group 0;\n");
        __syncthreads();   // tile t ready; also licenses overwrite of buf (t+2)%3
        if (t + 2 < nT) issue((t + 2) % 3, (t + 2) * 32);

        const __half* sA = As[t % 3];
        const __half* sB = Bs[t % 3];
#pragma unroll
        for (int kk = 0; kk < 2; kk++) {
            unsigned af[4][4], bf[8][2];
#pragma unroll
            for (int i = 0; i < 4; i++) {
                int mr = wm + i * 16 + lrow + a_r8;
                int ch = 2 * kk + a_cb;
                int sw = ch ^ ((mr >> 1) & 3);
                ldsm4(af[i][0], af[i][1], af[i][2], af[i][3], &sA[mr * 32 + sw * 8]);
            }
#pragma unroll
            for (int jp = 0; jp < 4; jp++) {
                int nr = wn + jp * 16 + lrow + b_r8;
                int ch = 2 * kk + b_cb;
                int sw = ch ^ ((nr >> 1) & 3);
                ldsm4(bf[2*jp][0], bf[2*jp][1], bf[2*jp+1][0], bf[2*jp+1][1],
                      &sB[nr * 32 + sw * 8]);
            }
#pragma unroll
            for (int i = 0; i < 4; i++)
#pragma unroll
                for (int j = 0; j < 8; j++)
                    mma_fp16(acc[i][j], af[i], bf[j]);
        }
    }

    // ---------------- epilogues ----------------
    if (EPI == 0) {
        int colBlock = n0 + wn;
        int qidx = colBlock >> 10;
        int head = (colBlock & 1023) >> 6;
#pragma unroll
        for (int i = 0; i < 4; i++) {
#pragma unroll
            for (int hh = 0; hh < 2; hh++) {
                int row = m0 + wm + i * 16 + g + hh * 8;
                int p = row & (N_TOK - 1);
#pragma unroll
                for (int j = 0; j < 4; j++) {
                    float o1[2], o2[2];
#pragma unroll
                    for (int cc = 0; cc < 2; cc++) {
                        int d = j * 8 + tg * 2 + cc;
                        float x1 = acc[i][j][hh * 2 + cc];
                        float x2 = acc[i][j + 4][hh * 2 + cc];
                        float cs = cosT[p * 32 + d];
                        float sn = sinT[p * 32 + d];
                        o1[cc] = x1 * cs - x2 * sn;
                        o2[cc] = x2 * cs + x1 * sn;
                    }
                    int d0 = j * 8 + tg * 2;
                    if (qidx == 0) {
                        __half* dst = Qp + ((size_t)head * S_TOK + row) * HD;
                        *(__half2*)&dst[d0]      = __floats2half2_rn(o1[0]*0.125f, o1[1]*0.125f);
                        *(__half2*)&dst[d0 + 32] = __floats2half2_rn(o2[0]*0.125f, o2[1]*0.125f);
                    } else if (qidx == 1) {
                        __half* dst = Kp + ((size_t)head * S_TOK + row) * HD;
                        *(__half2*)&dst[d0]      = __floats2half2_rn(o1[0], o1[1]);
                        *(__half2*)&dst[d0 + 32] = __floats2half2_rn(o2[0], o2[1]);
                    } else {
                        __half* dst = Vtp + (size_t)head * HD * S_TOK;
                        dst[(size_t)(d0)      * S_TOK + row] = __float2half(o1[0]);
                        dst[(size_t)(d0 + 1)  * S_TOK + row] = __float2half(o1[1]);
                        dst[(size_t)(d0 + 32) * S_TOK + row] = __float2half(o2[0]);
                        dst[(size_t)(d0 + 33) * S_TOK + row] = __float2half(o2[1]);
                    }
                }
            }
        }
        return;
    }

#pragma unroll
    for (int i = 0; i < 4; i++) {
        int row0 = m0 + wm + i * 16 + g;
#pragma unroll
        for (int j = 0; j < 8; j++) {
            int col = n0 + wn + j * 8 + tg * 2;
#pragma unroll
            for (int hh = 0; hh < 2; hh++) {
                int row = row0 + hh * 8;
                float v0 = acc[i][j][hh * 2 + 0];
                float v1 = acc[i][j][hh * 2 + 1];
                if (EPI == 1) {
                    float* C = (float*)Cout;
                    C[(size_t)row * N + col]     = gate[col] * v0 + res[(size_t)row * N + col];
                    C[(size_t)row * N + col + 1] = gate[col+1] * v1 + res[(size_t)row * N + col + 1];
                } else if (EPI == 2) {
                    __half* C = (__half*)Cout;
                    __half2 hv = __floats2half2_rn(gelu_tanh(v0 + bias[col]),
                                                   gelu_tanh(v1 + bias[col + 1]));
                    *(__half2*)&C[(size_t)row * N + col] = hv;
                } else {
                    float* C = (float*)Cout;
                    C[(size_t)row * N + col]     = gate[col] * (v0 + bias[col]) + res[(size_t)row * N + col];
                    C[(size_t)row * N + col + 1] = gate[col+1] * (v1 + bias[col+1]) + res[(size_t)row * N + col + 1];
                }
            }
        }
    }
}

// ---------------------------------------------------------------------------
// FP16 MMA block-diffusion attention (FlashAttention-2 style), as R7.
// ---------------------------------------------------------------------------
__global__ void __launch_bounds__(128)
attn_kernel(__half* __restrict__ O) {
    __shared__ __half Qs[16 * 64];
    __shared__ __half Ks[2][64 * 64];
    __shared__ __half Vs[2][64 * 64];   // Vt tile: [dim][key]

    const int qb = blockIdx.x;
    const int h  = blockIdx.y;
    const int t  = threadIdx.x;
    const int lane = t & 31;
    const int warp = t >> 5;
    const int g  = lane >> 2;
    const int tg = lane & 3;
    const int lrow = lane & 7;
    const int a_r8 = ((lane >> 3) & 1) * 8;
    const int a_cb = (lane >> 4) & 1;
    const int b_r8 = ((lane >> 4) & 1) * 8;
    const int b_cb = (lane >> 3) & 1;

    const int q0 = qb * 16;
    const __half* Qg = g_Qh + ((size_t)h * S_TOK + q0) * HD;
    const __half* Kg = g_Kh + (size_t)h * S_TOK * HD;
    const __half* Vg = g_Vt + (size_t)h * HD * S_TOK;

    const int t1n  = (qb < 64) ? 1 : 0;
    const int lenB = (qb < 64) ? qb * 16 : (qb - 63) * 16;
    const int nT   = t1n + ((lenB + 63) >> 6);

    auto tile_k0 = [&](int ti) {
        return (t1n && ti == 0) ? q0 : N_TOK + (ti - t1n) * 64;
    };
    auto tile_nv = [&](int ti) {
        return (t1n && ti == 0) ? 16 : min(64, lenB - (ti - t1n) * 64);
    };

    {
        int row = t >> 3, ch = t & 7;
        cp16(&Qs[row * 64 + (ch ^ (row & 7)) * 8], &Qg[row * 64 + ch * 8]);
    }
    auto issueKV = [&](int b, int k0) {
#pragma unroll
        for (int i = 0; i < 4; i++) {
            int idx = t + i * 128;
            int row = idx >> 3, ch = idx & 7;
            int sw  = (ch ^ (row & 7)) * 8;
            int src = min(k0 + row, S_TOK - 1);
            cp16(&Ks[b][row * 64 + sw], &Kg[(size_t)src * HD + ch * 8]);
            cp16(&Vs[b][row * 64 + sw], &Vg[(size_t)row * S_TOK + k0 + ch * 8]);
        }
        asm volatile("cp.async.commit_group;\n");
    };
    issueKV(0, tile_k0(0));

    unsigned aq[4][4];
    float Oacc[2][4] = {};
    float m0run = -INFINITY, m1run = -INFINITY;
    float l0run = 0.f, l1run = 0.f;

    for (int ti = 0; ti < nT; ti++) {
        asm volatile("cp.async.wait_group 0;\n");
        __syncthreads();
        if (ti == 0) {
#pragma unroll
            for (int kb = 0; kb < 4; kb++) {
                int r  = lrow + a_r8;
                int ch = 2 * kb + a_cb;
                ldsm4(aq[kb][0], aq[kb][1], aq[kb][2], aq[kb][3],
                      &Qs[r * 64 + (ch ^ (r & 7)) * 8]);
            }
        }
        if (ti + 1 < nT) issueKV((ti + 1) & 1, tile_k0(ti + 1));

        const __half* sK = Ks[ti & 1];
        const __half* sV = Vs[ti & 1];
        const int nv = tile_nv(ti);

        float sc[8][4] = {};
#pragma unroll
        for (int kb = 0; kb < 4; kb++) {
            unsigned bf[8][2];
#pragma unroll
            for (int pr = 0; pr < 4; pr++) {
                int r  = pr * 16 + lrow + b_r8;
                int ch = 2 * kb + b_cb;
                ldsm4(bf[2*pr][0], bf[2*pr][1], bf[2*pr+1][0], bf[2*pr+1][1],
                      &sK[r * 64 + (ch ^ (r & 7)) * 8]);
            }
#pragma unroll
            for (int nb = 0; nb < 8; nb++)
                mma_fp16(sc[nb], aq[kb], bf[nb]);
        }
#pragma unroll
        for (int nb = 0; nb < 8; nb++)
            if (nb * 8 >= nv) { sc[nb][0] = sc[nb][1] = sc[nb][2] = sc[nb][3] = -INFINITY; }

        float mx0 = -INFINITY, mx1 = -INFINITY;
#pragma unroll
        for (int nb = 0; nb < 8; nb++) {
            mx0 = fmaxf(mx0, fmaxf(sc[nb][0], sc[nb][1]));
            mx1 = fmaxf(mx1, fmaxf(sc[nb][2], sc[nb][3]));
        }
        mx0 = fmaxf(mx0, __shfl_xor_sync(0xffffffffu, mx0, 1));
        mx0 = fmaxf(mx0, __shfl_xor_sync(0xffffffffu, mx0, 2));
        mx1 = fmaxf(mx1, __shfl_xor_sync(0xffffffffu, mx1, 1));
        mx1 = fmaxf(mx1, __shfl_xor_sync(0xffffffffu, mx1, 2));

        float nm0 = fmaxf(m0run, mx0), nm1 = fmaxf(m1run, mx1);
        float c0 = __expf(m0run - nm0), c1 = __expf(m1run - nm1);
        float ts0 = 0.f, ts1 = 0.f;
#pragma unroll
        for (int nb = 0; nb < 8; nb++) {
            sc[nb][0] = __expf(sc[nb][0] - nm0);
            sc[nb][1] = __expf(sc[nb][1] - nm0);
            sc[nb][2] = __expf(sc[nb][2] - nm1);
            sc[nb][3] = __expf(sc[nb][3] - nm1);
            ts0 += sc[nb][0] + sc[nb][1];
            ts1 += sc[nb][2] + sc[nb][3];
        }
        ts0 += __shfl_xor_sync(0xffffffffu, ts0, 1);
        ts0 += __shfl_xor_sync(0xffffffffu, ts0, 2);
        ts1 += __shfl_xor_sync(0xffffffffu, ts1, 1);
        ts1 += __shfl_xor_sync(0xffffffffu, ts1, 2);
        l0run = l0run * c0 + ts0;  m0run = nm0;
        l1run = l1run * c1 + ts1;  m1run = nm1;

        Oacc[0][0] *= c0; Oacc[0][1] *= c0; Oacc[0][2] *= c1; Oacc[0][3] *= c1;
        Oacc[1][0] *= c0; Oacc[1][1] *= c0; Oacc[1][2] *= c1; Oacc[1][3] *= c1;

        unsigned ap[4][4];
#pragma unroll
        for (int kb2 = 0; kb2 < 4; kb2++) {
            ap[kb2][0] = packp(sc[2*kb2][0],   sc[2*kb2][1]);
            ap[kb2][1] = packp(sc[2*kb2][2],   sc[2*kb2][3]);
            ap[kb2][2] = packp(sc[2*kb2+1][0], sc[2*kb2+1][1]);
            ap[kb2][3] = packp(sc[2*kb2+1][2], sc[2*kb2+1][3]);
        }

#pragma unroll
        for (int kb2 = 0; kb2 < 4; kb2++) {
            unsigned bv0[2], bv1[2];
            int r  = warp * 16 + lrow + b_r8;
            int ch = 2 * kb2 + b_cb;
            ldsm4(bv0[0], bv0[1], bv1[0], bv1[1],
                  &sV[r * 64 + (ch ^ (r & 7)) * 8]);
            mma_fp16(Oacc[0], ap[kb2], bv0);
            mma_fp16(Oacc[1], ap[kb2], bv1);
        }
        __syncthreads();
    }

    float inv0 = 1.f / l0run, inv1 = 1.f / l1run;
    int row0 = q0 + g, row1 = q0 + g + 8;
#pragma unroll
    for (int nb2 = 0; nb2 < 2; nb2++) {
        int col = h * HD + warp * 16 + nb2 * 8 + tg * 2;
        *(__half2*)&O[(size_t)row0 * D_MODEL + col] =
            __floats2half2_rn(Oacc[nb2][0] * inv0, Oacc[nb2][1] * inv0);
        *(__half2*)&O[(size_t)row1 * D_MODEL + col] =
            __floats2half2_rn(Oacc[nb2][2] * inv1, Oacc[nb2][3] * inv1);
    }
}

// ---------------------------------------------------------------------------
// kernel_launch
// ---------------------------------------------------------------------------
extern "C" void kernel_launch(void* const* d_in, const int* in_sizes, int n_in,
                              void* d_out, int out_size) {
    const float* x          = (const float*)d_in[0];
    const float* c          = (const float*)d_in[1];
    const float* cosT       = (const float*)d_in[2];
    const float* sinT       = (const float*)d_in[3];
    const float* norm1_w    = (const float*)d_in[4];
    const float* qkv_w      = (const float*)d_in[5];
    const float* attn_out_w = (const float*)d_in[6];
    const float* norm2_w    = (const float*)d_in[7];
    const float* mlp_w1     = (const float*)d_in[8];
    const float* mlp_b1     = (const float*)d_in[9];
    const float* mlp_w2     = (const float*)d_in[10];
    const float* mlp_b2     = (const float*)d_in[11];
    const float* adaLN_w    = (const float*)d_in[12];
    const float* adaLN_b    = (const float*)d_in[13];
    float* out = (float*)d_out;

    float *mods, *x2;
    __half *h, *h2, *Oh, *m1, *Qp, *Kp, *Vtp, *wq, *wo, *w1, *w2;
    cudaGetSymbolAddress((void**)&mods, g_mods);
    cudaGetSymbolAddress((void**)&h,    g_h);
    cudaGetSymbolAddress((void**)&h2,   g_h2);
    cudaGetSymbolAddress((void**)&Oh,   g_Oh);
    cudaGetSymbolAddress((void**)&m1,   g_m1);
    cudaGetSymbolAddress((void**)&Qp,   g_Qh);
    cudaGetSymbolAddress((void**)&Kp,   g_Kh);
    cudaGetSymbolAddress((void**)&Vtp,  g_Vt);
    cudaGetSymbolAddress((void**)&x2,   g_x2);
    cudaGetSymbolAddress((void**)&wq,   g_wq);
    cudaGetSymbolAddress((void**)&wo,   g_wo);
    cudaGetSymbolAddress((void**)&w1,   g_w1);
    cudaGetSymbolAddress((void**)&w2,   g_w2);

    const float* sh_msa = mods + 0 * D_MODEL;
    const float* sc_msa = mods + 1 * D_MODEL;
    const float* g_msa  = mods + 2 * D_MODEL;
    const float* sh_mlp = mods + 3 * D_MODEL;
    const float* sc_mlp = mods + 4 * D_MODEL;
    const float* g_mlp  = mods + 5 * D_MODEL;

    f2h_all<<<(N4TOT + 255) / 256, 256>>>(qkv_w, attn_out_w, mlp_w1, mlp_w2);

    adaln_kernel<<<(6 * D_MODEL + 127) / 128, 128>>>(c, adaLN_w, adaLN_b);

    ln_mod_kernel<<<S_TOK, 256>>>(x, norm1_w, sc_msa, sh_msa, h);

    gemm16<0><<<dim3(3 * D_MODEL / 128, S_TOK / 128), 128>>>(
        h, wq, nullptr, S_TOK, 3 * D_MODEL, D_MODEL,
        nullptr, nullptr, nullptr, cosT, sinT, Qp, Kp, Vtp);

    attn_kernel<<<dim3(S_TOK / 16, H_HEADS), 128>>>(Oh);

    gemm16<1><<<dim3(D_MODEL / 128, S_TOK / 128), 128>>>(
        Oh, wo, x2, S_TOK, D_MODEL, D_MODEL,
        nullptr, g_msa, x, nullptr, nullptr, nullptr, nullptr, nullptr);

    ln_mod_kernel<<<S_TOK, 256>>>(x2, norm2_w, sc_mlp, sh_mlp, h2);

    gemm16<2><<<dim3(D_MLP / 128, S_TOK / 128), 128>>>(
        h2, w1, m1, S_TOK, D_MLP, D_MODEL,
        mlp_b1, nullptr, nullptr, nullptr, nullptr, nullptr, nullptr, nullptr);

    gemm16<3><<<dim3(D_MODEL / 128, S_TOK / 128), 128>>>(
        m1, w2, out, S_TOK, D_MODEL, D_MLP,
        mlp_b2, g_mlp, x2, nullptr, nullptr, nullptr, nullptr, nullptr);
}

// round 9
// speedup vs baseline: 9.0980x; 1.0039x over previous
#include <cuda_runtime.h>
#include <cuda_bf16.h>
#include <cuda_fp16.h>
#include <math.h>

// ---------------------------------------------------------------------------
// Problem constants
// ---------------------------------------------------------------------------
#define S_TOK   2048
#define N_TOK   1024
#define D_MODEL 1024
#define H_HEADS 16
#define HD      64
#define D_MLP   4096
#define COND    128
#define BSZ     16

// ---------------------------------------------------------------------------
// Device scratch
// ---------------------------------------------------------------------------
__device__ float  g_mods[6 * D_MODEL];
__device__ __half g_h  [S_TOK * D_MODEL];
__device__ __half g_h2 [S_TOK * D_MODEL];
__device__ __half g_Oh [S_TOK * D_MODEL];
__device__ __half g_m1 [S_TOK * D_MLP];
__device__ __half g_Qh [H_HEADS * S_TOK * HD];   // fp16, pre-scaled by 0.125
__device__ __half g_Kh [H_HEADS * S_TOK * HD];
__device__ __half g_Vt [H_HEADS * HD * S_TOK];   // TRANSPOSED: [head][dim][seq]
__device__ float  g_x2 [S_TOK * D_MODEL];
// fp16 weights (converted once per launch)
__device__ __half g_wq [3 * D_MODEL * D_MODEL];
__device__ __half g_wo [D_MODEL * D_MODEL];
__device__ __half g_w1 [D_MLP * D_MODEL];
__device__ __half g_w2 [D_MODEL * D_MLP];

// ---------------------------------------------------------------------------
// fp32 -> fp16 convert: all four weight arrays in ONE kernel
// ---------------------------------------------------------------------------
#define N4Q (3 * D_MODEL * D_MODEL / 4)
#define N4O (D_MODEL * D_MODEL / 4)
#define N4M (D_MLP * D_MODEL / 4)
#define N4TOT (N4Q + N4O + N4M + N4M)

__global__ void f2h_all(const float* __restrict__ wq, const float* __restrict__ wo,
                        const float* __restrict__ w1, const float* __restrict__ w2) {
    int i = blockIdx.x * blockDim.x + threadIdx.x;
    if (i >= N4TOT) return;
    const float* src;
    __half* dst;
    int off;
    if (i < N4Q)                { src = wq; dst = g_wq; off = i; }
    else if (i < N4Q + N4O)     { src = wo; dst = g_wo; off = i - N4Q; }
    else if (i < N4Q + N4O + N4M) { src = w1; dst = g_w1; off = i - N4Q - N4O; }
    else                        { src = w2; dst = g_w2; off = i - N4Q - N4O - N4M; }
    float4 v = ((const float4*)src)[off];
    __half2 h0 = __floats2half2_rn(v.x, v.y);
    __half2 h1 = __floats2half2_rn(v.z, v.w);
    ((__half2*)dst)[2 * off]     = h0;
    ((__half2*)dst)[2 * off + 1] = h1;
}

// ---------------------------------------------------------------------------
// adaLN
// ---------------------------------------------------------------------------
__global__ void adaln_kernel(const float* __restrict__ c,
                             const float* __restrict__ W,
                             const float* __restrict__ b) {
    __shared__ float cs[COND];
    int tid = threadIdx.x;
    if (tid < COND) cs[tid] = c[tid];
    __syncthreads();
    int i = blockIdx.x * blockDim.x + tid;
    if (i >= 6 * D_MODEL) return;
    const float* w = W + (size_t)i * COND;
    float acc = 0.f;
#pragma unroll 8
    for (int j = 0; j < COND; j++) acc += w[j] * cs[j];
    g_mods[i] = acc + b[i];
}

// ---------------------------------------------------------------------------
// LayerNorm + modulate -> fp16 output
// ---------------------------------------------------------------------------
__inline__ __device__ float warp_reduce_sum(float v) {
#pragma unroll
    for (int o = 16; o > 0; o >>= 1) v += __shfl_xor_sync(0xffffffffu, v, o);
    return v;
}

__global__ void ln_mod_kernel(const float* __restrict__ X,
                              const float* __restrict__ w,
                              const float* __restrict__ sc,
                              const float* __restrict__ sh,
                              __half* __restrict__ out) {
    int row = blockIdx.x;
    const float4* x4 = (const float4*)(X + (size_t)row * D_MODEL);
    int tid = threadIdx.x;
    float4 v = x4[tid];
    float s  = v.x + v.y + v.z + v.w;
    float ss = v.x*v.x + v.y*v.y + v.z*v.z + v.w*v.w;
    __shared__ float red_s[8], red_ss[8];
    s  = warp_reduce_sum(s);
    ss = warp_reduce_sum(ss);
    int wid = tid >> 5, lid = tid & 31;
    if (lid == 0) { red_s[wid] = s; red_ss[wid] = ss; }
    __syncthreads();
    if (wid == 0) {
        float a = (lid < 8) ? red_s[lid]  : 0.f;
        float b = (lid < 8) ? red_ss[lid] : 0.f;
        a = warp_reduce_sum(a);
        b = warp_reduce_sum(b);
        if (lid == 0) { red_s[0] = a; red_ss[0] = b; }
    }
    __syncthreads();
    float mu  = red_s[0] * (1.f / D_MODEL);
    float var = red_ss[0] * (1.f / D_MODEL) - mu * mu;
    float inv = rsqrtf(var + 1e-5f);
    int d0 = tid * 4;
    float vv[4] = {v.x, v.y, v.z, v.w};
    float o[4];
#pragma unroll
    for (int i = 0; i < 4; i++) {
        int d = d0 + i;
        o[i] = (vv[i] - mu) * inv * w[d] * (1.f + sc[d]) + sh[d];
    }
    __half2 h0 = __floats2half2_rn(o[0], o[1]);
    __half2 h1 = __floats2half2_rn(o[2], o[3]);
    *(__half2*)&out[(size_t)row * D_MODEL + d0]     = h0;
    *(__half2*)&out[(size_t)row * D_MODEL + d0 + 2] = h1;
}

// ---------------------------------------------------------------------------
// Common PTX helpers
// ---------------------------------------------------------------------------
__device__ __forceinline__ float gelu_tanh(float x) {
    float x3 = x * x * x;
    return 0.5f * x * (1.f + tanhf(0.7978845608028654f * (x + 0.044715f * x3)));
}

__device__ __forceinline__ void cp16(void* dst, const void* src) {
    unsigned d = (unsigned)__cvta_generic_to_shared(dst);
    asm volatile("cp.async.cg.shared.global [%0], [%1], 16;\n" :: "r"(d), "l"(src));
}

__device__ __forceinline__ void ldsm4(unsigned& r0, unsigned& r1, unsigned& r2, unsigned& r3,
                                      const __half* p) {
    unsigned a = (unsigned)__cvta_generic_to_shared(p);
    asm volatile("ldmatrix.sync.aligned.m8n8.x4.shared.b16 {%0,%1,%2,%3}, [%4];\n"
                 : "=r"(r0), "=r"(r1), "=r"(r2), "=r"(r3) : "r"(a));
}

__device__ __forceinline__ void mma_fp16(float* c, const unsigned* a, const unsigned* b) {
    asm volatile(
        "mma.sync.aligned.m16n8k16.row.col.f32.f16.f16.f32 "
        "{%0,%1,%2,%3}, {%4,%5,%6,%7}, {%8,%9}, {%0,%1,%2,%3};\n"
        : "+f"(c[0]), "+f"(c[1]), "+f"(c[2]), "+f"(c[3])
        : "r"(a[0]), "r"(a[1]), "r"(a[2]), "r"(a[3]), "r"(b[0]), "r"(b[1]));
}

__device__ __forceinline__ unsigned packp(float x, float y) {
    __half2 h = __floats2half2_rn(x, y);
    return *(unsigned*)&h;
}

// ---------------------------------------------------------------------------
// FP16 GEMM: 256 threads, 8 warps (4x2), warp tile 32x64, 3-stage cp.async
// pipeline, one barrier per k-tile. Regs capped at 128 -> 2 CTAs (16 warps)/SM.
// EPI: 0 qkv+rope -> Qh/Kh fp16 + Vt fp16 transposed, 1 gate*acc+res -> fp32,
//      2 gelu(acc+bias) -> fp16, 3 gate*(acc+bias)+res -> fp32
// ---------------------------------------------------------------------------
template<int EPI>
__global__ void __launch_bounds__(256, 2)
gemm16(const __half* __restrict__ A, const __half* __restrict__ B,
       void* __restrict__ Cout, int M, int N, int K,
       const float* __restrict__ bias, const float* __restrict__ gate,
       const float* __restrict__ res,
       const float* __restrict__ cosT, const float* __restrict__ sinT,
       __half* __restrict__ Qp, __half* __restrict__ Kp, __half* __restrict__ Vtp) {
    __shared__ __half As[3][128 * 32];
    __shared__ __half Bs[3][128 * 32];

    const int m0 = blockIdx.y * 128;
    const int n0 = blockIdx.x * 128;
    const int tid  = threadIdx.x;
    const int lane = tid & 31;
    const int warp = tid >> 5;
    const int wm = (warp >> 1) * 32;     // 0,32,64,96
    const int wn = (warp & 1) * 64;      // 0,64
    const int g  = lane >> 2;
    const int tg = lane & 3;
    const int sr  = tid >> 2;            // 0..63
    const int scn = tid & 3;

    float acc[2][8][4] = {};
    const int nT = K / 32;

    const int lrow = lane & 7;
    const int a_r8 = ((lane >> 3) & 1) * 8;
    const int a_cb = (lane >> 4) & 1;
    const int b_r8 = ((lane >> 4) & 1) * 8;
    const int b_cb = (lane >> 3) & 1;

    auto issue = [&](int b, int k0) {
#pragma unroll
        for (int i = 0; i < 2; i++) {
            int r  = sr + 64 * i;
            int sw = scn ^ ((r >> 1) & 3);
            cp16(&As[b][r * 32 + sw * 8], &A[(size_t)(m0 + r) * K + k0 + scn * 8]);
            cp16(&Bs[b][r * 32 + sw * 8], &B[(size_t)(n0 + r) * K + k0 + scn * 8]);
        }
        asm volatile("cp.async.commit_group;\n");
    };

    issue(0, 0);
    issue(1, 32);

    for (int t = 0; t < nT; t++) {
        if (t + 1 < nT) asm volatile("cp.async.wait_group 1;\n");
        else            asm volatile("cp.async.wait_group 0;\n");
        __syncthreads();   // tile t ready; also licenses overwrite of buf (t+2)%3
        if (t + 2 < nT) issue((t + 2) % 3, (t + 2) * 32);

        const __half* sA = As[t % 3];
        const __half* sB = Bs[t % 3];
#pragma unroll
        for (int kk = 0; kk < 2; kk++) {
            unsigned af[2][4], bf[8][2];
#pragma unroll
            for (int i = 0; i < 2; i++) {
                int mr = wm + i * 16 + lrow + a_r8;
                int ch = 2 * kk + a_cb;
                int sw = ch ^ ((mr >> 1) & 3);
                ldsm4(af[i][0], af[i][1], af[i][2], af[i][3], &sA[mr * 32 + sw * 8]);
            }
#pragma unroll
            for (int jp = 0; jp < 4; jp++) {
                int nr = wn + jp * 16 + lrow + b_r8;
                int ch = 2 * kk + b_cb;
                int sw = ch ^ ((nr >> 1) & 3);
                ldsm4(bf[2*jp][0], bf[2*jp][1], bf[2*jp+1][0], bf[2*jp+1][1],
                      &sB[nr * 32 + sw * 8]);
            }
#pragma unroll
            for (int i = 0; i < 2; i++)
#pragma unroll
                for (int j = 0; j < 8; j++)
                    mma_fp16(acc[i][j], af[i], bf[j]);
        }
    }

    // ---------------- epilogues ----------------
    if (EPI == 0) {
        int colBlock = n0 + wn;
        int qidx = colBlock >> 10;
        int head = (colBlock & 1023) >> 6;
#pragma unroll
        for (int i = 0; i < 2; i++) {
#pragma unroll
            for (int hh = 0; hh < 2; hh++) {
                int row = m0 + wm + i * 16 + g + hh * 8;
                int p = row & (N_TOK - 1);
#pragma unroll
                for (int j = 0; j < 4; j++) {
                    float o1[2], o2[2];
#pragma unroll
                    for (int cc = 0; cc < 2; cc++) {
                        int d = j * 8 + tg * 2 + cc;
                        float x1 = acc[i][j][hh * 2 + cc];
                        float x2 = acc[i][j + 4][hh * 2 + cc];
                        float cs = cosT[p * 32 + d];
                        float sn = sinT[p * 32 + d];
                        o1[cc] = x1 * cs - x2 * sn;
                        o2[cc] = x2 * cs + x1 * sn;
                    }
                    int d0 = j * 8 + tg * 2;
                    if (qidx == 0) {
                        __half* dst = Qp + ((size_t)head * S_TOK + row) * HD;
                        *(__half2*)&dst[d0]      = __floats2half2_rn(o1[0]*0.125f, o1[1]*0.125f);
                        *(__half2*)&dst[d0 + 32] = __floats2half2_rn(o2[0]*0.125f, o2[1]*0.125f);
                    } else if (qidx == 1) {
                        __half* dst = Kp + ((size_t)head * S_TOK + row) * HD;
                        *(__half2*)&dst[d0]      = __floats2half2_rn(o1[0], o1[1]);
                        *(__half2*)&dst[d0 + 32] = __floats2half2_rn(o2[0], o2[1]);
                    } else {
                        __half* dst = Vtp + (size_t)head * HD * S_TOK;
                        dst[(size_t)(d0)      * S_TOK + row] = __float2half(o1[0]);
                        dst[(size_t)(d0 + 1)  * S_TOK + row] = __float2half(o1[1]);
                        dst[(size_t)(d0 + 32) * S_TOK + row] = __float2half(o2[0]);
                        dst[(size_t)(d0 + 33) * S_TOK + row] = __float2half(o2[1]);
                    }
                }
            }
        }
        return;
    }

#pragma unroll
    for (int i = 0; i < 2; i++) {
        int row0 = m0 + wm + i * 16 + g;
#pragma unroll
        for (int j = 0; j < 8; j++) {
            int col = n0 + wn + j * 8 + tg * 2;
#pragma unroll
            for (int hh = 0; hh < 2; hh++) {
                int row = row0 + hh * 8;
                float v0 = acc[i][j][hh * 2 + 0];
                float v1 = acc[i][j][hh * 2 + 1];
                if (EPI == 1) {
                    float* C = (float*)Cout;
                    C[(size_t)row * N + col]     = gate[col] * v0 + res[(size_t)row * N + col];
                    C[(size_t)row * N + col + 1] = gate[col+1] * v1 + res[(size_t)row * N + col + 1];
                } else if (EPI == 2) {
                    __half* C = (__half*)Cout;
                    __half2 hv = __floats2half2_rn(gelu_tanh(v0 + bias[col]),
                                                   gelu_tanh(v1 + bias[col + 1]));
                    *(__half2*)&C[(size_t)row * N + col] = hv;
                } else {
                    float* C = (float*)Cout;
                    C[(size_t)row * N + col]     = gate[col] * (v0 + bias[col]) + res[(size_t)row * N + col];
                    C[(size_t)row * N + col + 1] = gate[col+1] * (v1 + bias[col+1]) + res[(size_t)row * N + col + 1];
                }
            }
        }
    }
}

// ---------------------------------------------------------------------------
// FP16 MMA block-diffusion attention (FlashAttention-2 style), as R7.
// ---------------------------------------------------------------------------
__global__ void __launch_bounds__(128)
attn_kernel(__half* __restrict__ O) {
    __shared__ __half Qs[16 * 64];
    __shared__ __half Ks[2][64 * 64];
    __shared__ __half Vs[2][64 * 64];   // Vt tile: [dim][key]

    const int qb = blockIdx.x;
    const int h  = blockIdx.y;
    const int t  = threadIdx.x;
    const int lane = t & 31;
    const int warp = t >> 5;
    const int g  = lane >> 2;
    const int tg = lane & 3;
    const int lrow = lane & 7;
    const int a_r8 = ((lane >> 3) & 1) * 8;
    const int a_cb = (lane >> 4) & 1;
    const int b_r8 = ((lane >> 4) & 1) * 8;
    const int b_cb = (lane >> 3) & 1;

    const int q0 = qb * 16;
    const __half* Qg = g_Qh + ((size_t)h * S_TOK + q0) * HD;
    const __half* Kg = g_Kh + (size_t)h * S_TOK * HD;
    const __half* Vg = g_Vt + (size_t)h * HD * S_TOK;

    const int t1n  = (qb < 64) ? 1 : 0;
    const int lenB = (qb < 64) ? qb * 16 : (qb - 63) * 16;
    const int nT   = t1n + ((lenB + 63) >> 6);

    auto tile_k0 = [&](int ti) {
        return (t1n && ti == 0) ? q0 : N_TOK + (ti - t1n) * 64;
    };
    auto tile_nv = [&](int ti) {
        return (t1n && ti == 0) ? 16 : min(64, lenB - (ti - t1n) * 64);
    };

    {
        int row = t >> 3, ch = t & 7;
        cp16(&Qs[row * 64 + (ch ^ (row & 7)) * 8], &Qg[row * 64 + ch * 8]);
    }
    auto issueKV = [&](int b, int k0) {
#pragma unroll
        for (int i = 0; i < 4; i++) {
            int idx = t + i * 128;
            int row = idx >> 3, ch = idx & 7;
            int sw  = (ch ^ (row & 7)) * 8;
            int src = min(k0 + row, S_TOK - 1);
            cp16(&Ks[b][row * 64 + sw], &Kg[(size_t)src * HD + ch * 8]);
            cp16(&Vs[b][row * 64 + sw], &Vg[(size_t)row * S_TOK + k0 + ch * 8]);
        }
        asm volatile("cp.async.commit_group;\n");
    };
    issueKV(0, tile_k0(0));

    unsigned aq[4][4];
    float Oacc[2][4] = {};
    float m0run = -INFINITY, m1run = -INFINITY;
    float l0run = 0.f, l1run = 0.f;

    for (int ti = 0; ti < nT; ti++) {
        asm volatile("cp.async.wait_group 0;\n");
        __syncthreads();
        if (ti == 0) {
#pragma unroll
            for (int kb = 0; kb < 4; kb++) {
                int r  = lrow + a_r8;
                int ch = 2 * kb + a_cb;
                ldsm4(aq[kb][0], aq[kb][1], aq[kb][2], aq[kb][3],
                      &Qs[r * 64 + (ch ^ (r & 7)) * 8]);
            }
        }
        if (ti + 1 < nT) issueKV((ti + 1) & 1, tile_k0(ti + 1));

        const __half* sK = Ks[ti & 1];
        const __half* sV = Vs[ti & 1];
        const int nv = tile_nv(ti);

        float sc[8][4] = {};
#pragma unroll
        for (int kb = 0; kb < 4; kb++) {
            unsigned bf[8][2];
#pragma unroll
            for (int pr = 0; pr < 4; pr++) {
                int r  = pr * 16 + lrow + b_r8;
                int ch = 2 * kb + b_cb;
                ldsm4(bf[2*pr][0], bf[2*pr][1], bf[2*pr+1][0], bf[2*pr+1][1],
                      &sK[r * 64 + (ch ^ (r & 7)) * 8]);
            }
#pragma unroll
            for (int nb = 0; nb < 8; nb++)
                mma_fp16(sc[nb], aq[kb], bf[nb]);
        }
#pragma unroll
        for (int nb = 0; nb < 8; nb++)
            if (nb * 8 >= nv) { sc[nb][0] = sc[nb][1] = sc[nb][2] = sc[nb][3] = -INFINITY; }

        float mx0 = -INFINITY, mx1 = -INFINITY;
#pragma unroll
        for (int nb = 0; nb < 8; nb++) {
            mx0 = fmaxf(mx0, fmaxf(sc[nb][0], sc[nb][1]));
            mx1 = fmaxf(mx1, fmaxf(sc[nb][2], sc[nb][3]));
        }
        mx0 = fmaxf(mx0, __shfl_xor_sync(0xffffffffu, mx0, 1));
        mx0 = fmaxf(mx0, __shfl_xor_sync(0xffffffffu, mx0, 2));
        mx1 = fmaxf(mx1, __shfl_xor_sync(0xffffffffu, mx1, 1));
        mx1 = fmaxf(mx1, __shfl_xor_sync(0xffffffffu, mx1, 2));

        float nm0 = fmaxf(m0run, mx0), nm1 = fmaxf(m1run, mx1);
        float c0 = __expf(m0run - nm0), c1 = __expf(m1run - nm1);
        float ts0 = 0.f, ts1 = 0.f;
#pragma unroll
        for (int nb = 0; nb < 8; nb++) {
            sc[nb][0] = __expf(sc[nb][0] - nm0);
            sc[nb][1] = __expf(sc[nb][1] - nm0);
            sc[nb][2] = __expf(sc[nb][2] - nm1);
            sc[nb][3] = __expf(sc[nb][3] - nm1);
            ts0 += sc[nb][0] + sc[nb][1];
            ts1 += sc[nb][2] + sc[nb][3];
        }
        ts0 += __shfl_xor_sync(0xffffffffu, ts0, 1);
        ts0 += __shfl_xor_sync(0xffffffffu, ts0, 2);
        ts1 += __shfl_xor_sync(0xffffffffu, ts1, 1);
        ts1 += __shfl_xor_sync(0xffffffffu, ts1, 2);
        l0run = l0run * c0 + ts0;  m0run = nm0;
        l1run = l1run * c1 + ts1;  m1run = nm1;

        Oacc[0][0] *= c0; Oacc[0][1] *= c0; Oacc[0][2] *= c1; Oacc[0][3] *= c1;
        Oacc[1][0] *= c0; Oacc[1][1] *= c0; Oacc[1][2] *= c1; Oacc[1][3] *= c1;

        unsigned ap[4][4];
#pragma unroll
        for (int kb2 = 0; kb2 < 4; kb2++) {
            ap[kb2][0] = packp(sc[2*kb2][0],   sc[2*kb2][1]);
            ap[kb2][1] = packp(sc[2*kb2][2],   sc[2*kb2][3]);
            ap[kb2][2] = packp(sc[2*kb2+1][0], sc[2*kb2+1][1]);
            ap[kb2][3] = packp(sc[2*kb2+1][2], sc[2*kb2+1][3]);
        }

#pragma unroll
        for (int kb2 = 0; kb2 < 4; kb2++) {
            unsigned bv0[2], bv1[2];
            int r  = warp * 16 + lrow + b_r8;
            int ch = 2 * kb2 + b_cb;
            ldsm4(bv0[0], bv0[1], bv1[0], bv1[1],
                  &sV[r * 64 + (ch ^ (r & 7)) * 8]);
            mma_fp16(Oacc[0], ap[kb2], bv0);
            mma_fp16(Oacc[1], ap[kb2], bv1);
        }
        __syncthreads();
    }

    float inv0 = 1.f / l0run, inv1 = 1.f / l1run;
    int row0 = q0 + g, row1 = q0 + g + 8;
#pragma unroll
    for (int nb2 = 0; nb2 < 2; nb2++) {
        int col = h * HD + warp * 16 + nb2 * 8 + tg * 2;
        *(__half2*)&O[(size_t)row0 * D_MODEL + col] =
            __floats2half2_rn(Oacc[nb2][0] * inv0, Oacc[nb2][1] * inv0);
        *(__half2*)&O[(size_t)row1 * D_MODEL + col] =
            __floats2half2_rn(Oacc[nb2][2] * inv1, Oacc[nb2][3] * inv1);
    }
}

// ---------------------------------------------------------------------------
// kernel_launch
// ---------------------------------------------------------------------------
extern "C" void kernel_launch(void* const* d_in, const int* in_sizes, int n_in,
                              void* d_out, int out_size) {
    const float* x          = (const float*)d_in[0];
    const float* c          = (const float*)d_in[1];
    const float* cosT       = (const float*)d_in[2];
    const float* sinT       = (const float*)d_in[3];
    const float* norm1_w    = (const float*)d_in[4];
    const float* qkv_w      = (const float*)d_in[5];
    const float* attn_out_w = (const float*)d_in[6];
    const float* norm2_w    = (const float*)d_in[7];
    const float* mlp_w1     = (const float*)d_in[8];
    const float* mlp_b1     = (const float*)d_in[9];
    const float* mlp_w2     = (const float*)d_in[10];
    const float* mlp_b2     = (const float*)d_in[11];
    const float* adaLN_w    = (const float*)d_in[12];
    const float* adaLN_b    = (const float*)d_in[13];
    float* out = (float*)d_out;

    float *mods, *x2;
    __half *h, *h2, *Oh, *m1, *Qp, *Kp, *Vtp, *wq, *wo, *w1, *w2;
    cudaGetSymbolAddress((void**)&mods, g_mods);
    cudaGetSymbolAddress((void**)&h,    g_h);
    cudaGetSymbolAddress((void**)&h2,   g_h2);
    cudaGetSymbolAddress((void**)&Oh,   g_Oh);
    cudaGetSymbolAddress((void**)&m1,   g_m1);
    cudaGetSymbolAddress((void**)&Qp,   g_Qh);
    cudaGetSymbolAddress((void**)&Kp,   g_Kh);
    cudaGetSymbolAddress((void**)&Vtp,  g_Vt);
    cudaGetSymbolAddress((void**)&x2,   g_x2);
    cudaGetSymbolAddress((void**)&wq,   g_wq);
    cudaGetSymbolAddress((void**)&wo,   g_wo);
    cudaGetSymbolAddress((void**)&w1,   g_w1);
    cudaGetSymbolAddress((void**)&w2,   g_w2);

    const float* sh_msa = mods + 0 * D_MODEL;
    const float* sc_msa = mods + 1 * D_MODEL;
    const float* g_msa  = mods + 2 * D_MODEL;
    const float* sh_mlp = mods + 3 * D_MODEL;
    const float* sc_mlp = mods + 4 * D_MODEL;
    const float* g_mlp  = mods + 5 * D_MODEL;

    f2h_all<<<(N4TOT + 255) / 256, 256>>>(qkv_w, attn_out_w, mlp_w1, mlp_w2);

    adaln_kernel<<<(6 * D_MODEL + 127) / 128, 128>>>(c, adaLN_w, adaLN_b);

    ln_mod_kernel<<<S_TOK, 256>>>(x, norm1_w, sc_msa, sh_msa, h);

    gemm16<0><<<dim3(3 * D_MODEL / 128, S_TOK / 128), 256>>>(
        h, wq, nullptr, S_TOK, 3 * D_MODEL, D_MODEL,
        nullptr, nullptr, nullptr, cosT, sinT, Qp, Kp, Vtp);

    attn_kernel<<<dim3(S_TOK / 16, H_HEADS), 128>>>(Oh);

    gemm16<1><<<dim3(D_MODEL / 128, S_TOK / 128), 256>>>(
        Oh, wo, x2, S_TOK, D_MODEL, D_MODEL,
        nullptr, g_msa, x, nullptr, nullptr, nullptr, nullptr, nullptr);

    ln_mod_kernel<<<S_TOK, 256>>>(x2, norm2_w, sc_mlp, sh_mlp, h2);

    gemm16<2><<<dim3(D_MLP / 128, S_TOK / 128), 256>>>(
        h2, w1, m1, S_TOK, D_MLP, D_MODEL,
        mlp_b1, nullptr, nullptr, nullptr, nullptr, nullptr, nullptr, nullptr);

    gemm16<3><<<dim3(D_MODEL / 128, S_TOK / 128), 256>>>(
        m1, w2, out, S_TOK, D_MODEL, D_MLP,
        mlp_b2, g_mlp, x2, nullptr, nullptr, nullptr, nullptr, nullptr);
}